// round 15
// baseline (speedup 1.0000x reference)
#include <cuda_runtime.h>
#include <cuda_bf16.h>
#include <math.h>

// Problem constants
// E=2 streams, B=8, H=W=64, C=64, DI=128, L=4096, K=4 dirs, R=4, N=1
#define EB 16            // E*B
#define L_ 4096
#define DI_ 128
#define C_ 64
#define CH 64            // scan chunks per sequence
#define CLEN 64          // chunk length (CH*CLEN = L)

// ---------------- scratch (static __device__, no allocation) ----------------
__device__ float g_xcpre[EB * L_ * DI_];     // pre-conv x branch [eb][s][d]
__device__ float g_z    [EB * L_ * DI_];     // silu(z)           [eb][s][d]
__device__ float g_xc   [EB * L_ * DI_];     // conv+silu output  [eb][s][d]
__device__ float g_rec  [EB * 4 * L_ * 8];   // per (eb,k,j): dt0..3, Bs, Cs, pad2
__device__ float g_aggA [64 * CH * DI_];     // chunk aggregate A
__device__ float g_aggB [64 * CH * DI_];     // chunk aggregate B
__device__ float g_pref [64 * CH * DI_];     // incoming prefix per chunk
__device__ float g_ysA  [EB * L_ * DI_];     // y(dir0)+y(dir2), spatial order
__device__ float g_ysB  [EB * L_ * DI_];     // y(dir1)+y(dir3), j-order
__device__ float g_xres [EB * L_ * C_];      // residual after attention part
__device__ float g_mlp  [EB * L_ * C_];      // per-stream final output
// packed bf16 hi/lo weights (built by k0_prep each call)
__device__ uint2 g_w1p[2 * 256 * 32];        // f1w pairs: [(e,n)][k/2] -> (hi2, lo2)
__device__ uint2 g_w2p[2 * 64 * 128];        // f2w pairs
__device__ uint2 g_wip[2 * 256 * 32];        // in_proj pairs
__device__ uint2 g_wop[2 * 64 * 64];         // out_proj pairs

__device__ __forceinline__ int ltmap(int j) { return ((j & 63) << 6) | (j >> 6); }

__device__ __forceinline__ float siluf(float v) {
    return v / (1.f + __expf(-v));
}
__device__ __forceinline__ float sp(float x) {   // softplus, stable + fast
    return fmaxf(x, 0.f) + __logf(1.f + __expf(-fabsf(x)));
}
__device__ __forceinline__ float geluf(float v) {
    return 0.5f * v * (1.f + erff(v * 0.70710678118654752f));
}

// ---------------- bf16 mma helpers ------------------------------------------
__device__ __forceinline__ void mma16816(float c[4],
    unsigned a0, unsigned a1, unsigned a2, unsigned a3,
    unsigned b0, unsigned b1)
{
    asm("mma.sync.aligned.m16n8k16.row.col.f32.bf16.bf16.f32 "
        "{%0,%1,%2,%3}, {%4,%5,%6,%7}, {%8,%9}, {%0,%1,%2,%3};"
        : "+f"(c[0]), "+f"(c[1]), "+f"(c[2]), "+f"(c[3])
        : "r"(a0), "r"(a1), "r"(a2), "r"(a3), "r"(b0), "r"(b1));
}
__device__ __forceinline__ unsigned pkbf(float a, float b) {
    unsigned short ua = __bfloat16_as_ushort(__float2bfloat16(a));
    unsigned short ub = __bfloat16_as_ushort(__float2bfloat16(b));
    return (unsigned)ua | ((unsigned)ub << 16);
}

// ------------- K0: split GEMM weights to packed bf16 hi/lo ------------------
__global__ void k0_prep(const float* __restrict__ f1w, const float* __restrict__ f2w,
                        const float* __restrict__ ipw, const float* __restrict__ opw)
{
    int i = blockIdx.x * 256 + threadIdx.x;     // 0..57343
    const float* src; uint2* dst; int p;
    if (i < 16384)      { src = f1w; dst = g_w1p; p = i; }
    else if (i < 32768) { src = f2w; dst = g_w2p; p = i - 16384; }
    else if (i < 49152) { src = ipw; dst = g_wip; p = i - 32768; }
    else                { src = opw; dst = g_wop; p = i - 49152; }
    float a0 = src[2 * p], a1 = src[2 * p + 1];
    __nv_bfloat16 h0 = __float2bfloat16(a0), h1 = __float2bfloat16(a1);
    float l0 = a0 - __bfloat162float(h0);
    float l1 = a1 - __bfloat162float(h1);
    unsigned hi = (unsigned)__bfloat16_as_ushort(h0) | ((unsigned)__bfloat16_as_ushort(h1) << 16);
    unsigned lo = pkbf(l0, l1);
    dst[p] = make_uint2(hi, lo);
}

// ------ K1: LN + in_proj (64->256) via tensor cores, split, silu(z) ---------
__global__ __launch_bounds__(128) void k1_mma(
    const float* __restrict__ mag, const float* __restrict__ phase,
    const float* __restrict__ n1w, const float* __restrict__ n1b)
{
    __shared__ float sxf[32 * 64];
    __shared__ __nv_bfloat16 sAh[32 * 72];
    __shared__ __nv_bfloat16 sAl[32 * 72];
    __shared__ float smu[32], srs[32];
    int row0 = blockIdx.x * 32;
    int e = row0 >> 15;
    const float* xin = e ? phase : mag;
    int rloc0 = row0 & 32767;
    int t = threadIdx.x;
    int lane = t & 31, wid = t >> 5;
    int group = lane >> 2, tig = lane & 3;
    {
        int r = t >> 2, c0 = (t & 3) * 16;
        #pragma unroll
        for (int i = 0; i < 4; i++) {
            float4 v = *(const float4*)&xin[(rloc0 + r) * 64 + c0 + 4 * i];
            sxf[r * 64 + c0 + 4*i + 0] = v.x; sxf[r * 64 + c0 + 4*i + 1] = v.y;
            sxf[r * 64 + c0 + 4*i + 2] = v.z; sxf[r * 64 + c0 + 4*i + 3] = v.w;
        }
    }
    __syncthreads();
    if (t < 32) {
        float s = 0.f, s2 = 0.f;
        #pragma unroll
        for (int i = 0; i < 64; i++) { float v = sxf[t * 64 + i]; s += v; s2 += v * v; }
        float mu = s * (1.f / 64.f);
        smu[t] = mu;
        srs[t] = rsqrtf(fmaxf(s2 * (1.f / 64.f) - mu * mu, 0.f) + 1e-5f);
    }
    __syncthreads();
    #pragma unroll
    for (int idx = 0; idx < 16; idx++) {
        int q = idx * 128 + t;
        int rr = q >> 6, cc = q & 63;
        float v = (sxf[rr * 64 + cc] - smu[rr]) * srs[rr] * n1w[e * 64 + cc] + n1b[e * 64 + cc];
        __nv_bfloat16 h = __float2bfloat16(v);
        sAh[rr * 72 + cc] = h;
        sAl[rr * 72 + cc] = __float2bfloat16(v - __bfloat162float(h));
    }
    __syncthreads();
    // GEMM C[32,256] = A[32,64] * Wip^T  (warps: mt = row-tile, nb = col-half)
    int mt = wid & 1;
    int nb = (wid >> 1) * 128;
    float c1[16][4];
    #pragma unroll
    for (int i = 0; i < 16; i++)
        { c1[i][0] = 0.f; c1[i][1] = 0.f; c1[i][2] = 0.f; c1[i][3] = 0.f; }
    #pragma unroll
    for (int ks = 0; ks < 4; ks++) {
        int ar = mt * 16 + group;
        int kk = ks * 16 + tig * 2;
        unsigned ah0 = *(const unsigned*)(sAh + ar * 72 + kk);
        unsigned ah1 = *(const unsigned*)(sAh + (ar + 8) * 72 + kk);
        unsigned ah2 = *(const unsigned*)(sAh + ar * 72 + kk + 8);
        unsigned ah3 = *(const unsigned*)(sAh + (ar + 8) * 72 + kk + 8);
        unsigned al0 = *(const unsigned*)(sAl + ar * 72 + kk);
        unsigned al1 = *(const unsigned*)(sAl + (ar + 8) * 72 + kk);
        unsigned al2 = *(const unsigned*)(sAl + ar * 72 + kk + 8);
        unsigned al3 = *(const unsigned*)(sAl + (ar + 8) * 72 + kk + 8);
        const uint2* wbase = g_wip + (size_t)(e * 256 + nb + group) * 32 + ks * 8 + tig;
        #pragma unroll
        for (int nt = 0; nt < 16; nt++) {
            const uint2* wp = wbase + nt * 256;
            uint2 v0 = wp[0];
            uint2 v1 = wp[4];
            mma16816(c1[nt], ah0, ah1, ah2, ah3, v0.x, v1.x);
            mma16816(c1[nt], ah0, ah1, ah2, ah3, v0.y, v1.y);
            mma16816(c1[nt], al0, al1, al2, al3, v0.x, v1.x);
        }
    }
    // store: cols <128 -> g_xcpre ; cols >=128 -> silu -> g_z (uniform per warp)
    if (nb == 0) {
        #pragma unroll
        for (int nt = 0; nt < 16; nt++) {
            int colb = nt * 8 + tig * 2;
            int r0 = row0 + mt * 16 + group;
            *(float2*)&g_xcpre[r0 * 128 + colb]       = make_float2(c1[nt][0], c1[nt][1]);
            *(float2*)&g_xcpre[(r0 + 8) * 128 + colb] = make_float2(c1[nt][2], c1[nt][3]);
        }
    } else {
        #pragma unroll
        for (int nt = 0; nt < 16; nt++) {
            int colb = nt * 8 + tig * 2;
            int r0 = row0 + mt * 16 + group;
            *(float2*)&g_z[r0 * 128 + colb]       = make_float2(siluf(c1[nt][0]), siluf(c1[nt][1]));
            *(float2*)&g_z[(r0 + 8) * 128 + colb] = make_float2(siluf(c1[nt][2]), siluf(c1[nt][3]));
        }
    }
}

// ------ K2: depthwise 3x3 conv + silu — rolling window along w --------------
__global__ __launch_bounds__(128) void k2_conv(const float* __restrict__ cw)
{
    int blk = blockIdx.x;            // eb*64 + h
    int h = blk & 63;
    int eb = blk >> 6;
    int e = eb >> 3;
    int d = threadIdx.x;
    const float* base = g_xcpre + (size_t)eb * 4096 * 128 + d;
    float* outp = g_xc + (size_t)(eb * 4096 + h * 64) * 128 + d;
    const float* wk = &cw[(e * 128 + d) * 9];
    float w00 = wk[0], w01 = wk[1], w02 = wk[2];
    float w10 = wk[3], w11 = wk[4], w12 = wk[5];
    float w20 = wk[6], w21 = wk[7], w22 = wk[8];
    bool hm = (h > 0), hp = (h < 63);
    const float* rm = base + (size_t)((h - 1) * 64) * 128;
    const float* r0 = base + (size_t)(h * 64) * 128;
    const float* rp = base + (size_t)((h + 1) * 64) * 128;
    float a0 = 0.f, a1 = 0.f, a2 = 0.f;                 // col w-1
    float b0 = hm ? rm[0] : 0.f, b1 = r0[0], b2 = hp ? rp[0] : 0.f;   // col w
    float c0 = hm ? rm[128] : 0.f, c1 = r0[128], c2 = hp ? rp[128] : 0.f; // col w+1
    #pragma unroll 4
    for (int w = 0; w < 64; w++) {
        float acc = w00 * a0;
        acc = fmaf(w10, a1, acc);
        acc = fmaf(w20, a2, acc);
        acc = fmaf(w01, b0, acc);
        acc = fmaf(w11, b1, acc);
        acc = fmaf(w21, b2, acc);
        acc = fmaf(w02, c0, acc);
        acc = fmaf(w12, c1, acc);
        acc = fmaf(w22, c2, acc);
        outp[(size_t)w * 128] = siluf(acc);
        a0 = b0; a1 = b1; a2 = b2;
        b0 = c0; b1 = c1; b2 = c2;
        if (w + 2 < 64) {
            size_t off = (size_t)(w + 2) * 128;
            c0 = hm ? rm[off] : 0.f;
            c1 = r0[off];
            c2 = hp ? rp[off] : 0.f;
        } else { c0 = 0.f; c1 = 0.f; c2 = 0.f; }
    }
}

// ---- K3: x_proj (128 -> 6) — lane=(pos, quarter), 2-step reduction ---------
// Warp covers 8 positions; each lane computes 6 partial dots over its 32
// channels, then reduces across 4 q-lanes (12 SHFL per 8 outputs vs 240).
__global__ __launch_bounds__(256) void k3_xdbl(const float* __restrict__ xprojw)
{
    int gw = blockIdx.x * 8 + (threadIdx.x >> 5);  // 0..32767
    int lane = threadIdx.x & 31;
    int p = lane >> 2, q = lane & 3;
    int j0 = (gw & 511) * 8;
    int k = (gw >> 9) & 3;
    int b = (gw >> 11) & 7;
    int e = gw >> 14;
    int j = j0 + p;
    int jj = (k >= 2) ? 4095 - j : j;
    int pos = (k & 1) ? ltmap(jj) : jj;
    const float* xr = g_xc + (size_t)(e * 8 + b) * 4096 * 128 + (size_t)pos * 128 + q * 32;
    const float* wb = xprojw + (size_t)((e * 4 + k) * 6) * 128 + q * 32;
    float dot[6] = {0.f, 0.f, 0.f, 0.f, 0.f, 0.f};
    #pragma unroll
    for (int i = 0; i < 8; i++) {
        float4 x4 = *(const float4*)(xr + i * 4);
        #pragma unroll
        for (int c = 0; c < 6; c++) {
            float4 w4 = *(const float4*)(wb + c * 128 + i * 4);
            dot[c] = fmaf(x4.x, w4.x, dot[c]);
            dot[c] = fmaf(x4.y, w4.y, dot[c]);
            dot[c] = fmaf(x4.z, w4.z, dot[c]);
            dot[c] = fmaf(x4.w, w4.w, dot[c]);
        }
    }
    #pragma unroll
    for (int off = 1; off <= 2; off <<= 1) {
        #pragma unroll
        for (int c = 0; c < 6; c++)
            dot[c] += __shfl_xor_sync(0xffffffffu, dot[c], off);
    }
    if (q == 0) {
        float* rp = g_rec + (size_t)(((e * 8 + b) * 4 + k) * 4096 + j) * 8;
        *(float4*)rp       = make_float4(dot[0], dot[1], dot[2], dot[3]);
        *(float2*)(rp + 4) = make_float2(dot[4], dot[5]);
    }
}

// -- K4a: scan pass 1 — per-chunk aggregates, 2 interleaved chains/thread ----
__global__ __launch_bounds__(128) void k4a_scan_partial(
    const float* __restrict__ dtw, const float* __restrict__ dtb,
    const float* __restrict__ alogs)
{
    int blk = blockIdx.x;                 // ebk*32 + cp  (2 chunks per block)
    int cp = blk & 31;
    int ebk = blk >> 5;
    int k = ebk & 3, b = (ebk >> 2) & 7, e = ebk >> 5;
    int d = threadIdx.x;
    int kd = (e * 4 + k) * 128 + d;
    float4 w4 = *(const float4*)&dtw[kd * 4];
    float bias = dtb[kd];
    float Aval = -expf(alogs[kd]);
    const float* xb = g_xc + (size_t)(e * 8 + b) * 4096 * 128;
    const float* rec = g_rec + (size_t)((e * 8 + b) * 4 + k) * 4096 * 8;
    int j0 = cp * 2 * CLEN;
    int j1 = j0 + CLEN;
    float Ap0 = 1.f, Bp0 = 0.f, Ap1 = 1.f, Bp1 = 0.f;
    #pragma unroll 2
    for (int i = 0; i < CLEN; i++) {
        {   // chain 0
            int j = j0 + i;
            int jm = (k >= 2) ? 4095 - j : j;
            int pos = (k & 1) ? ltmap(jm) : jm;
            float4 r4 = *(const float4*)(rec + (size_t)j * 8);
            float Bs = rec[(size_t)j * 8 + 4];
            float x = xb[(size_t)pos * 128 + d];
            float zz = fmaf(w4.x, r4.x, fmaf(w4.y, r4.y, fmaf(w4.z, r4.z, fmaf(w4.w, r4.w, bias))));
            float delta = sp(zz);
            float a = __expf(delta * Aval);
            Bp0 = fmaf(Bp0, a, delta * Bs * x);
            Ap0 *= a;
        }
        {   // chain 1
            int j = j1 + i;
            int jm = (k >= 2) ? 4095 - j : j;
            int pos = (k & 1) ? ltmap(jm) : jm;
            float4 r4 = *(const float4*)(rec + (size_t)j * 8);
            float Bs = rec[(size_t)j * 8 + 4];
            float x = xb[(size_t)pos * 128 + d];
            float zz = fmaf(w4.x, r4.x, fmaf(w4.y, r4.y, fmaf(w4.z, r4.z, fmaf(w4.w, r4.w, bias))));
            float delta = sp(zz);
            float a = __expf(delta * Aval);
            Bp1 = fmaf(Bp1, a, delta * Bs * x);
            Ap1 *= a;
        }
    }
    g_aggA[(ebk * CH + cp * 2) * 128 + d] = Ap0;
    g_aggB[(ebk * CH + cp * 2) * 128 + d] = Bp0;
    g_aggA[(ebk * CH + cp * 2 + 1) * 128 + d] = Ap1;
    g_aggB[(ebk * CH + cp * 2 + 1) * 128 + d] = Bp1;
}

// ---------------- K4b: scan pass 2 — prefix across chunks -------------------
__global__ void k4b_scan_prefix()
{
    int ebk = blockIdx.x;    // 0..63
    int d = threadIdx.x;
    float h = 0.f;
    #pragma unroll
    for (int c = 0; c < CH; c++) {
        int idx = (ebk * CH + c) * 128 + d;
        float A = g_aggA[idx], Bv = g_aggB[idx];
        g_pref[idx] = h;
        h = fmaf(A, h, Bv);
    }
}

// ----- K4c: scan pass 3 — paired dirs (p, p+2), summed plane, NO smem -------
__global__ __launch_bounds__(128) void k4c_pair(
    const float* __restrict__ dtw, const float* __restrict__ dtb,
    const float* __restrict__ alogs, const float* __restrict__ dsv)
{
    int blk = blockIdx.x;                // eb*128 + p*64 + hc
    int hc = blk & 63;
    int p = (blk >> 6) & 1;
    int eb = blk >> 7;
    int e = eb >> 3;
    int d = threadIdx.x;
    int kf = p, kb = p + 2;
    int ebkf = eb * 4 + kf, ebkb = eb * 4 + kb;
    int kdf = (e * 4 + kf) * 128 + d;
    int kdb = (e * 4 + kb) * 128 + d;
    float4 wf = *(const float4*)&dtw[kdf * 4];
    float4 wb = *(const float4*)&dtw[kdb * 4];
    float biasf = dtb[kdf], biasb = dtb[kdb];
    float Avf = -expf(alogs[kdf]), Avb = -expf(alogs[kdb]);
    float Dvf = dsv[kdf], Dvb = dsv[kdb];
    const float* xb = g_xc + (size_t)eb * 4096 * 128;
    const float* recf = g_rec + (size_t)ebkf * 4096 * 8;
    const float* recb = g_rec + (size_t)ebkb * 4096 * 8;
    float* outp = (p ? g_ysB : g_ysA) + ((size_t)eb * 4096 + hc * CLEN) * 128 + d;
    // dir p+2, its chunk (63-hc), time-forward = i descending; write y2
    float hb = g_pref[(ebkb * CH + (CH - 1 - hc)) * 128 + d];
    #pragma unroll 4
    for (int i = CLEN - 1; i >= 0; i--) {
        int jj = hc * CLEN + i;
        int pos = p ? ltmap(jj) : jj;
        int jb = 4095 - jj;
        const float* rp = recb + (size_t)jb * 8;
        float4 r4 = *(const float4*)rp;
        float Bs = rp[4], Cs = rp[5];
        float x = xb[(size_t)pos * 128 + d];
        float zz = fmaf(wb.x, r4.x, fmaf(wb.y, r4.y, fmaf(wb.z, r4.z, fmaf(wb.w, r4.w, biasb))));
        float delta = sp(zz);
        float a = __expf(delta * Avb);
        hb = fmaf(a, hb, delta * Bs * x);
        outp[(size_t)i * 128] = fmaf(hb, Cs, Dvb * x);
    }
    // dir p, chunk hc, forward; add y1
    float hf = g_pref[(ebkf * CH + hc) * 128 + d];
    #pragma unroll 4
    for (int i = 0; i < CLEN; i++) {
        int jj = hc * CLEN + i;
        int pos = p ? ltmap(jj) : jj;
        const float* rp = recf + (size_t)jj * 8;
        float4 r4 = *(const float4*)rp;
        float Bs = rp[4], Cs = rp[5];
        float x = xb[(size_t)pos * 128 + d];
        float zz = fmaf(wf.x, r4.x, fmaf(wf.y, r4.y, fmaf(wf.z, r4.z, fmaf(wf.w, r4.w, biasf))));
        float delta = sp(zz);
        float a = __expf(delta * Avf);
        hf = fmaf(a, hf, delta * Bs * x);
        float y1 = fmaf(hf, Cs, Dvf * x);
        outp[(size_t)i * 128] += y1;
    }
}

// -- K6: sum 2 planes + LN*z + out_proj (128->64) via tensor cores + resid ---
__global__ __launch_bounds__(128) void k6_mma(
    const float* __restrict__ mag, const float* __restrict__ phase,
    const float* __restrict__ onw, const float* __restrict__ onb)
{
    __shared__ float syf[32 * 128];
    __shared__ __nv_bfloat16 sAh[32 * 136];
    __shared__ __nv_bfloat16 sAl[32 * 136];
    __shared__ float smu[32], srs[32];
    int row0 = blockIdx.x * 32;
    int e = row0 >> 15;
    int ebbase = row0 & ~4095;       // eb*4096
    int t = threadIdx.x;
    int lane = t & 31, wid = t >> 5;
    int group = lane >> 2, tig = lane & 3;
    {
        int r = t >> 2, c0 = (t & 3) * 32;
        int s = (row0 & 4095) + r;
        int jj = ltmap(s);
        const float* pA = &g_ysA[(size_t)(row0 + r) * 128 + c0];
        const float* pB = &g_ysB[(size_t)(ebbase + jj) * 128 + c0];
        #pragma unroll
        for (int i = 0; i < 8; i++) {
            float4 vA = *(const float4*)&pA[4 * i];
            float4 vB = *(const float4*)&pB[4 * i];
            syf[r * 128 + c0 + 4*i + 0] = vA.x + vB.x;
            syf[r * 128 + c0 + 4*i + 1] = vA.y + vB.y;
            syf[r * 128 + c0 + 4*i + 2] = vA.z + vB.z;
            syf[r * 128 + c0 + 4*i + 3] = vA.w + vB.w;
        }
    }
    __syncthreads();
    if (t < 32) {
        float s = 0.f, s2 = 0.f;
        #pragma unroll 8
        for (int i = 0; i < 128; i++) { float v = syf[t * 128 + i]; s += v; s2 += v * v; }
        float mu = s * (1.f / 128.f);
        smu[t] = mu;
        srs[t] = rsqrtf(fmaxf(s2 * (1.f / 128.f) - mu * mu, 0.f) + 1e-5f);
    }
    __syncthreads();
    #pragma unroll
    for (int idx = 0; idx < 32; idx++) {
        int q = idx * 128 + t;
        int rr = q >> 7, cc = q & 127;
        float v = (syf[rr * 128 + cc] - smu[rr]) * srs[rr] * onw[e * 128 + cc] + onb[e * 128 + cc];
        v *= g_z[(size_t)(row0 + rr) * 128 + cc];
        __nv_bfloat16 h = __float2bfloat16(v);
        sAh[rr * 136 + cc] = h;
        sAl[rr * 136 + cc] = __float2bfloat16(v - __bfloat162float(h));
    }
    __syncthreads();
    // GEMM C[32,64] = A[32,128] * Wop^T
    int mt = wid & 1;
    int nb2 = (wid >> 1) * 32;
    float c2[4][4];
    #pragma unroll
    for (int i = 0; i < 4; i++)
        { c2[i][0] = 0.f; c2[i][1] = 0.f; c2[i][2] = 0.f; c2[i][3] = 0.f; }
    #pragma unroll
    for (int ks = 0; ks < 8; ks++) {
        int ar = mt * 16 + group;
        int kk = ks * 16 + tig * 2;
        unsigned ah0 = *(const unsigned*)(sAh + ar * 136 + kk);
        unsigned ah1 = *(const unsigned*)(sAh + (ar + 8) * 136 + kk);
        unsigned ah2 = *(const unsigned*)(sAh + ar * 136 + kk + 8);
        unsigned ah3 = *(const unsigned*)(sAh + (ar + 8) * 136 + kk + 8);
        unsigned al0 = *(const unsigned*)(sAl + ar * 136 + kk);
        unsigned al1 = *(const unsigned*)(sAl + (ar + 8) * 136 + kk);
        unsigned al2 = *(const unsigned*)(sAl + ar * 136 + kk + 8);
        unsigned al3 = *(const unsigned*)(sAl + (ar + 8) * 136 + kk + 8);
        const uint2* wbase = g_wop + (size_t)(e * 64 + nb2 + group) * 64 + ks * 8 + tig;
        #pragma unroll
        for (int nt = 0; nt < 4; nt++) {
            const uint2* wp = wbase + nt * 512;   // n += 8 -> +8*64 pairs
            uint2 v0 = wp[0];
            uint2 v1 = wp[4];
            mma16816(c2[nt], ah0, ah1, ah2, ah3, v0.x, v1.x);
            mma16816(c2[nt], ah0, ah1, ah2, ah3, v0.y, v1.y);
            mma16816(c2[nt], al0, al1, al2, al3, v0.x, v1.x);
        }
    }
    const float* xin = e ? phase : mag;
    int rl0 = row0 & 32767;
    #pragma unroll
    for (int nt = 0; nt < 4; nt++) {
        int colb = nb2 + nt * 8 + tig * 2;
        int r0 = mt * 16 + group;
        float2 x0 = *(const float2*)&xin[(rl0 + r0) * 64 + colb];
        float2 x1 = *(const float2*)&xin[(rl0 + r0 + 8) * 64 + colb];
        *(float2*)&g_xres[(row0 + r0) * 64 + colb] =
            make_float2(c2[nt][0] + x0.x, c2[nt][1] + x0.y);
        *(float2*)&g_xres[(row0 + r0 + 8) * 64 + colb] =
            make_float2(c2[nt][2] + x1.x, c2[nt][3] + x1.y);
    }
}

// -------- K7: LN + fc1 + gelu + fc2 + residual — tensor-core bf16 split -----
__global__ __launch_bounds__(128) void k7_mlp_mma(
    const float* __restrict__ n2w, const float* __restrict__ n2b,
    const float* __restrict__ f1b, const float* __restrict__ f2b)
{
    __shared__ __align__(16) unsigned char smraw[43264];
    float* sxf = (float*)smraw;                              // 32x64 f32 (early)
    __nv_bfloat16* sHh = (__nv_bfloat16*)smraw;              // 32x264
    __nv_bfloat16* sHl = (__nv_bfloat16*)(smraw + 16896);
    __nv_bfloat16* sAh = (__nv_bfloat16*)(smraw + 33792);    // 32x72
    __nv_bfloat16* sAl = (__nv_bfloat16*)(smraw + 38400);
    float* smu = (float*)(smraw + 43008);
    float* srs = (float*)(smraw + 43136);

    int row0 = blockIdx.x * 32;
    int e = row0 >> 15;
    int t = threadIdx.x;
    int lane = t & 31, wid = t >> 5;
    int group = lane >> 2, tig = lane & 3;

    {
        int r = t >> 2, c0 = (t & 3) * 16;
        #pragma unroll
        for (int i = 0; i < 4; i++) {
            float4 v = *(const float4*)&g_xres[(row0 + r) * 64 + c0 + 4 * i];
            sxf[r * 64 + c0 + 4*i + 0] = v.x; sxf[r * 64 + c0 + 4*i + 1] = v.y;
            sxf[r * 64 + c0 + 4*i + 2] = v.z; sxf[r * 64 + c0 + 4*i + 3] = v.w;
        }
    }
    __syncthreads();
    if (t < 32) {
        float s = 0.f, s2 = 0.f;
        #pragma unroll
        for (int i = 0; i < 64; i++) { float v = sxf[t * 64 + i]; s += v; s2 += v * v; }
        float mu = s * (1.f / 64.f);
        smu[t] = mu;
        srs[t] = rsqrtf(fmaxf(s2 * (1.f / 64.f) - mu * mu, 0.f) + 1e-5f);
    }
    __syncthreads();
    #pragma unroll
    for (int idx = 0; idx < 16; idx++) {
        int q = idx * 128 + t;           // 0..2047
        int rr = q >> 6, cc = q & 63;
        float v = (sxf[rr * 64 + cc] - smu[rr]) * srs[rr] * n2w[e * 64 + cc] + n2b[e * 64 + cc];
        __nv_bfloat16 h = __float2bfloat16(v);
        sAh[rr * 72 + cc] = h;
        sAl[rr * 72 + cc] = __float2bfloat16(v - __bfloat162float(h));
    }
    __syncthreads();

    // fc1
    int mt = wid & 1;
    int nb = (wid >> 1) * 128;
    float c1[16][4];
    #pragma unroll
    for (int i = 0; i < 16; i++)
        { c1[i][0] = 0.f; c1[i][1] = 0.f; c1[i][2] = 0.f; c1[i][3] = 0.f; }
    #pragma unroll
    for (int ks = 0; ks < 4; ks++) {
        int ar = mt * 16 + group;
        int kk = ks * 16 + tig * 2;
        unsigned ah0 = *(const unsigned*)(sAh + ar * 72 + kk);
        unsigned ah1 = *(const unsigned*)(sAh + (ar + 8) * 72 + kk);
        unsigned ah2 = *(const unsigned*)(sAh + ar * 72 + kk + 8);
        unsigned ah3 = *(const unsigned*)(sAh + (ar + 8) * 72 + kk + 8);
        unsigned al0 = *(const unsigned*)(sAl + ar * 72 + kk);
        unsigned al1 = *(const unsigned*)(sAl + (ar + 8) * 72 + kk);
        unsigned al2 = *(const unsigned*)(sAl + ar * 72 + kk + 8);
        unsigned al3 = *(const unsigned*)(sAl + (ar + 8) * 72 + kk + 8);
        const uint2* wbase = g_w1p + (size_t)(e * 256 + nb + group) * 32 + ks * 8 + tig;
        #pragma unroll
        for (int nt = 0; nt < 16; nt++) {
            const uint2* wp = wbase + nt * 256;
            uint2 v0 = wp[0];
            uint2 v1 = wp[4];
            mma16816(c1[nt], ah0, ah1, ah2, ah3, v0.x, v1.x);
            mma16816(c1[nt], ah0, ah1, ah2, ah3, v0.y, v1.y);
            mma16816(c1[nt], al0, al1, al2, al3, v0.x, v1.x);
        }
    }
    #pragma unroll
    for (int nt = 0; nt < 16; nt++) {
        int colb = nb + nt * 8 + tig * 2;
        float2 b1 = *(const float2*)&f1b[e * 256 + colb];
        int r0 = mt * 16 + group;
        float g00 = geluf(c1[nt][0] + b1.x);
        float g01 = geluf(c1[nt][1] + b1.y);
        float g10 = geluf(c1[nt][2] + b1.x);
        float g11 = geluf(c1[nt][3] + b1.y);
        __nv_bfloat16 h;
        h = __float2bfloat16(g00); sHh[r0 * 264 + colb]           = h; sHl[r0 * 264 + colb]           = __float2bfloat16(g00 - __bfloat162float(h));
        h = __float2bfloat16(g01); sHh[r0 * 264 + colb + 1]       = h; sHl[r0 * 264 + colb + 1]       = __float2bfloat16(g01 - __bfloat162float(h));
        h = __float2bfloat16(g10); sHh[(r0 + 8) * 264 + colb]     = h; sHl[(r0 + 8) * 264 + colb]     = __float2bfloat16(g10 - __bfloat162float(h));
        h = __float2bfloat16(g11); sHh[(r0 + 8) * 264 + colb + 1] = h; sHl[(r0 + 8) * 264 + colb + 1] = __float2bfloat16(g11 - __bfloat162float(h));
    }
    __syncthreads();

    // fc2
    int nb2 = (wid >> 1) * 32;
    float c2[4][4];
    #pragma unroll
    for (int i = 0; i < 4; i++)
        { c2[i][0] = 0.f; c2[i][1] = 0.f; c2[i][2] = 0.f; c2[i][3] = 0.f; }
    #pragma unroll 4
    for (int ks = 0; ks < 16; ks++) {
        int ar = mt * 16 + group;
        int kk = ks * 16 + tig * 2;
        unsigned ah0 = *(const unsigned*)(sHh + ar * 264 + kk);
        unsigned ah1 = *(const unsigned*)(sHh + (ar + 8) * 264 + kk);
        unsigned ah2 = *(const unsigned*)(sHh + ar * 264 + kk + 8);
        unsigned ah3 = *(const unsigned*)(sHh + (ar + 8) * 264 + kk + 8);
        unsigned al0 = *(const unsigned*)(sHl + ar * 264 + kk);
        unsigned al1 = *(const unsigned*)(sHl + (ar + 8) * 264 + kk);
        unsigned al2 = *(const unsigned*)(sHl + ar * 264 + kk + 8);
        unsigned al3 = *(const unsigned*)(sHl + (ar + 8) * 264 + kk + 8);
        const uint2* wbase = g_w2p + (size_t)(e * 64 + nb2 + group) * 128 + ks * 8 + tig;
        #pragma unroll
        for (int nt = 0; nt < 4; nt++) {
            const uint2* wp = wbase + nt * 1024;
            uint2 v0 = wp[0];
            uint2 v1 = wp[4];
            mma16816(c2[nt], ah0, ah1, ah2, ah3, v0.x, v1.x);
            mma16816(c2[nt], ah0, ah1, ah2, ah3, v0.y, v1.y);
            mma16816(c2[nt], al0, al1, al2, al3, v0.x, v1.x);
        }
    }
    #pragma unroll
    for (int nt = 0; nt < 4; nt++) {
        int colb = nb2 + nt * 8 + tig * 2;
        float2 b2 = *(const float2*)&f2b[e * 64 + colb];
        int r0g = row0 + mt * 16 + group;
        float2 x0 = *(const float2*)&g_xres[r0g * 64 + colb];
        float2 x1 = *(const float2*)&g_xres[(r0g + 8) * 64 + colb];
        float2 o0 = make_float2(x0.x + c2[nt][0] + b2.x, x0.y + c2[nt][1] + b2.y);
        float2 o1 = make_float2(x1.x + c2[nt][2] + b2.x, x1.y + c2[nt][3] + b2.y);
        *(float2*)&g_mlp[r0g * 64 + colb] = o0;
        *(float2*)&g_mlp[(r0g + 8) * 64 + colb] = o1;
    }
}

// ---------------- K8: sum streams, duplicate output (float4) ----------------
__global__ void k8_final(float* __restrict__ out)
{
    int i = blockIdx.x * 256 + threadIdx.x;   // 0..524287 (float4 units)
    float4 a = *(const float4*)&g_mlp[4 * i];
    float4 b = *(const float4*)&g_mlp[4 * i + 2097152];
    float4 s = make_float4(a.x + b.x, a.y + b.y, a.z + b.z, a.w + b.w);
    *(float4*)&out[4 * i] = s;
    *(float4*)&out[4 * i + 2097152] = s;
}

// ---------------- launch ----------------------------------------------------
extern "C" void kernel_launch(void* const* d_in, const int* in_sizes, int n_in,
                              void* d_out, int out_size)
{
    const float* mag   = (const float*)d_in[0];
    const float* phase = (const float*)d_in[1];
    const float* n1w   = (const float*)d_in[2];
    const float* n1b   = (const float*)d_in[3];
    const float* ipw   = (const float*)d_in[4];
    const float* cvw   = (const float*)d_in[5];
    const float* xpw   = (const float*)d_in[6];
    const float* dtw   = (const float*)d_in[7];
    const float* dtb   = (const float*)d_in[8];
    const float* alg   = (const float*)d_in[9];
    const float* dsv   = (const float*)d_in[10];
    const float* onw   = (const float*)d_in[11];
    const float* onb   = (const float*)d_in[12];
    const float* opw   = (const float*)d_in[13];
    const float* n2w   = (const float*)d_in[14];
    const float* n2b   = (const float*)d_in[15];
    const float* f1w   = (const float*)d_in[16];
    const float* f1b   = (const float*)d_in[17];
    const float* f2w   = (const float*)d_in[18];
    const float* f2b   = (const float*)d_in[19];

    k0_prep<<<224, 256>>>(f1w, f2w, ipw, opw);
    k1_mma<<<2048, 128>>>(mag, phase, n1w, n1b);
    k2_conv<<<1024, 128>>>(cvw);
    k3_xdbl<<<4096, 256>>>(xpw);
    k4a_scan_partial<<<2048, 128>>>(dtw, dtb, alg);
    k4b_scan_prefix<<<64, 128>>>();
    k4c_pair<<<2048, 128>>>(dtw, dtb, alg, dsv);
    k6_mma<<<2048, 128>>>(mag, phase, onw, onb);
    k7_mlp_mma<<<2048, 128>>>(n2w, n2b, f1b, f2b);
    k8_final<<<2048, 256>>>((float*)d_out);
}

// round 16
// speedup vs baseline: 1.1880x; 1.1880x over previous
#include <cuda_runtime.h>
#include <cuda_bf16.h>
#include <math.h>

// Problem constants
// E=2 streams, B=8, H=W=64, C=64, DI=128, L=4096, K=4 dirs, R=4, N=1
#define EB 16            // E*B
#define L_ 4096
#define DI_ 128
#define C_ 64
#define CH 64            // scan chunks per sequence
#define CLEN 64          // chunk length (CH*CLEN = L)

// ---------------- scratch (static __device__, no allocation) ----------------
__device__ float g_xcpre[EB * L_ * DI_];     // pre-conv x branch [eb][s][d]
__device__ float g_z    [EB * L_ * DI_];     // silu(z)           [eb][s][d]
__device__ float g_xc   [EB * L_ * DI_];     // conv+silu output  [eb][s][d]
__device__ float g_rec  [EB * 4 * L_ * 8];   // per (eb,k,j): dt0..3, Bs, Cs, pad2
__device__ float g_aggA [64 * CH * DI_];     // chunk aggregate A
__device__ float g_aggB [64 * CH * DI_];     // chunk aggregate B
__device__ float g_pref [64 * CH * DI_];     // incoming prefix per chunk
__device__ float g_ysA  [EB * L_ * DI_];     // y(dir0)+y(dir2), spatial order
__device__ float g_ysB  [EB * L_ * DI_];     // y(dir1)+y(dir3), j-order
__device__ float g_xres [EB * L_ * C_];      // residual after attention part
__device__ float g_mlp  [EB * L_ * C_];      // per-stream final output
// packed bf16 hi/lo weights (built by k0_prep each call)
__device__ uint2 g_w1p[2 * 256 * 32];        // f1w pairs: [(e,n)][k/2] -> (hi2, lo2)
__device__ uint2 g_w2p[2 * 64 * 128];        // f2w pairs
__device__ uint2 g_wip[2 * 256 * 32];        // in_proj pairs
__device__ uint2 g_wop[2 * 64 * 64];         // out_proj pairs

__device__ __forceinline__ int ltmap(int j) { return ((j & 63) << 6) | (j >> 6); }

__device__ __forceinline__ float siluf(float v) {
    return v / (1.f + __expf(-v));
}
__device__ __forceinline__ float sp(float x) {   // softplus, stable + fast
    return fmaxf(x, 0.f) + __logf(1.f + __expf(-fabsf(x)));
}
__device__ __forceinline__ float geluf(float v) {
    return 0.5f * v * (1.f + erff(v * 0.70710678118654752f));
}

// ---------------- bf16 mma helpers ------------------------------------------
__device__ __forceinline__ void mma16816(float c[4],
    unsigned a0, unsigned a1, unsigned a2, unsigned a3,
    unsigned b0, unsigned b1)
{
    asm("mma.sync.aligned.m16n8k16.row.col.f32.bf16.bf16.f32 "
        "{%0,%1,%2,%3}, {%4,%5,%6,%7}, {%8,%9}, {%0,%1,%2,%3};"
        : "+f"(c[0]), "+f"(c[1]), "+f"(c[2]), "+f"(c[3])
        : "r"(a0), "r"(a1), "r"(a2), "r"(a3), "r"(b0), "r"(b1));
}
__device__ __forceinline__ unsigned pkbf(float a, float b) {
    unsigned short ua = __bfloat16_as_ushort(__float2bfloat16(a));
    unsigned short ub = __bfloat16_as_ushort(__float2bfloat16(b));
    return (unsigned)ua | ((unsigned)ub << 16);
}

// ------------- K0: split GEMM weights to packed bf16 hi/lo ------------------
__global__ void k0_prep(const float* __restrict__ f1w, const float* __restrict__ f2w,
                        const float* __restrict__ ipw, const float* __restrict__ opw)
{
    int i = blockIdx.x * 256 + threadIdx.x;     // 0..57343
    const float* src; uint2* dst; int p;
    if (i < 16384)      { src = f1w; dst = g_w1p; p = i; }
    else if (i < 32768) { src = f2w; dst = g_w2p; p = i - 16384; }
    else if (i < 49152) { src = ipw; dst = g_wip; p = i - 32768; }
    else                { src = opw; dst = g_wop; p = i - 49152; }
    float a0 = src[2 * p], a1 = src[2 * p + 1];
    __nv_bfloat16 h0 = __float2bfloat16(a0), h1 = __float2bfloat16(a1);
    float l0 = a0 - __bfloat162float(h0);
    float l1 = a1 - __bfloat162float(h1);
    unsigned hi = (unsigned)__bfloat16_as_ushort(h0) | ((unsigned)__bfloat16_as_ushort(h1) << 16);
    unsigned lo = pkbf(l0, l1);
    dst[p] = make_uint2(hi, lo);
}

// ------ K1: LN + in_proj (64->256) via tensor cores, split, silu(z) ---------
__global__ __launch_bounds__(128) void k1_mma(
    const float* __restrict__ mag, const float* __restrict__ phase,
    const float* __restrict__ n1w, const float* __restrict__ n1b)
{
    __shared__ float sxf[32 * 64];
    __shared__ __nv_bfloat16 sAh[32 * 72];
    __shared__ __nv_bfloat16 sAl[32 * 72];
    __shared__ float smu[32], srs[32];
    int row0 = blockIdx.x * 32;
    int e = row0 >> 15;
    const float* xin = e ? phase : mag;
    int rloc0 = row0 & 32767;
    int t = threadIdx.x;
    int lane = t & 31, wid = t >> 5;
    int group = lane >> 2, tig = lane & 3;
    {
        int r = t >> 2, c0 = (t & 3) * 16;
        #pragma unroll
        for (int i = 0; i < 4; i++) {
            float4 v = *(const float4*)&xin[(rloc0 + r) * 64 + c0 + 4 * i];
            sxf[r * 64 + c0 + 4*i + 0] = v.x; sxf[r * 64 + c0 + 4*i + 1] = v.y;
            sxf[r * 64 + c0 + 4*i + 2] = v.z; sxf[r * 64 + c0 + 4*i + 3] = v.w;
        }
    }
    __syncthreads();
    if (t < 32) {
        float s = 0.f, s2 = 0.f;
        #pragma unroll
        for (int i = 0; i < 64; i++) { float v = sxf[t * 64 + i]; s += v; s2 += v * v; }
        float mu = s * (1.f / 64.f);
        smu[t] = mu;
        srs[t] = rsqrtf(fmaxf(s2 * (1.f / 64.f) - mu * mu, 0.f) + 1e-5f);
    }
    __syncthreads();
    #pragma unroll
    for (int idx = 0; idx < 16; idx++) {
        int q = idx * 128 + t;
        int rr = q >> 6, cc = q & 63;
        float v = (sxf[rr * 64 + cc] - smu[rr]) * srs[rr] * n1w[e * 64 + cc] + n1b[e * 64 + cc];
        __nv_bfloat16 h = __float2bfloat16(v);
        sAh[rr * 72 + cc] = h;
        sAl[rr * 72 + cc] = __float2bfloat16(v - __bfloat162float(h));
    }
    __syncthreads();
    // GEMM C[32,256] = A[32,64] * Wip^T  (warps: mt = row-tile, nb = col-half)
    int mt = wid & 1;
    int nb = (wid >> 1) * 128;
    float c1[16][4];
    #pragma unroll
    for (int i = 0; i < 16; i++)
        { c1[i][0] = 0.f; c1[i][1] = 0.f; c1[i][2] = 0.f; c1[i][3] = 0.f; }
    #pragma unroll
    for (int ks = 0; ks < 4; ks++) {
        int ar = mt * 16 + group;
        int kk = ks * 16 + tig * 2;
        unsigned ah0 = *(const unsigned*)(sAh + ar * 72 + kk);
        unsigned ah1 = *(const unsigned*)(sAh + (ar + 8) * 72 + kk);
        unsigned ah2 = *(const unsigned*)(sAh + ar * 72 + kk + 8);
        unsigned ah3 = *(const unsigned*)(sAh + (ar + 8) * 72 + kk + 8);
        unsigned al0 = *(const unsigned*)(sAl + ar * 72 + kk);
        unsigned al1 = *(const unsigned*)(sAl + (ar + 8) * 72 + kk);
        unsigned al2 = *(const unsigned*)(sAl + ar * 72 + kk + 8);
        unsigned al3 = *(const unsigned*)(sAl + (ar + 8) * 72 + kk + 8);
        const uint2* wbase = g_wip + (size_t)(e * 256 + nb + group) * 32 + ks * 8 + tig;
        #pragma unroll
        for (int nt = 0; nt < 16; nt++) {
            const uint2* wp = wbase + nt * 256;
            uint2 v0 = wp[0];
            uint2 v1 = wp[4];
            mma16816(c1[nt], ah0, ah1, ah2, ah3, v0.x, v1.x);
            mma16816(c1[nt], ah0, ah1, ah2, ah3, v0.y, v1.y);
            mma16816(c1[nt], al0, al1, al2, al3, v0.x, v1.x);
        }
    }
    // store: cols <128 -> g_xcpre ; cols >=128 -> silu -> g_z (uniform per warp)
    if (nb == 0) {
        #pragma unroll
        for (int nt = 0; nt < 16; nt++) {
            int colb = nt * 8 + tig * 2;
            int r0 = row0 + mt * 16 + group;
            *(float2*)&g_xcpre[r0 * 128 + colb]       = make_float2(c1[nt][0], c1[nt][1]);
            *(float2*)&g_xcpre[(r0 + 8) * 128 + colb] = make_float2(c1[nt][2], c1[nt][3]);
        }
    } else {
        #pragma unroll
        for (int nt = 0; nt < 16; nt++) {
            int colb = nt * 8 + tig * 2;
            int r0 = row0 + mt * 16 + group;
            *(float2*)&g_z[r0 * 128 + colb]       = make_float2(siluf(c1[nt][0]), siluf(c1[nt][1]));
            *(float2*)&g_z[(r0 + 8) * 128 + colb] = make_float2(siluf(c1[nt][2]), siluf(c1[nt][3]));
        }
    }
}

// ------ K2: depthwise 3x3 conv + silu — rolling window along w --------------
__global__ __launch_bounds__(128) void k2_conv(const float* __restrict__ cw)
{
    int blk = blockIdx.x;            // eb*64 + h
    int h = blk & 63;
    int eb = blk >> 6;
    int e = eb >> 3;
    int d = threadIdx.x;
    const float* base = g_xcpre + (size_t)eb * 4096 * 128 + d;
    float* outp = g_xc + (size_t)(eb * 4096 + h * 64) * 128 + d;
    const float* wk = &cw[(e * 128 + d) * 9];
    float w00 = wk[0], w01 = wk[1], w02 = wk[2];
    float w10 = wk[3], w11 = wk[4], w12 = wk[5];
    float w20 = wk[6], w21 = wk[7], w22 = wk[8];
    bool hm = (h > 0), hp = (h < 63);
    const float* rm = base + (size_t)((h - 1) * 64) * 128;
    const float* r0 = base + (size_t)(h * 64) * 128;
    const float* rp = base + (size_t)((h + 1) * 64) * 128;
    float a0 = 0.f, a1 = 0.f, a2 = 0.f;                 // col w-1
    float b0 = hm ? rm[0] : 0.f, b1 = r0[0], b2 = hp ? rp[0] : 0.f;   // col w
    float c0 = hm ? rm[128] : 0.f, c1 = r0[128], c2 = hp ? rp[128] : 0.f; // col w+1
    #pragma unroll 4
    for (int w = 0; w < 64; w++) {
        float acc = w00 * a0;
        acc = fmaf(w10, a1, acc);
        acc = fmaf(w20, a2, acc);
        acc = fmaf(w01, b0, acc);
        acc = fmaf(w11, b1, acc);
        acc = fmaf(w21, b2, acc);
        acc = fmaf(w02, c0, acc);
        acc = fmaf(w12, c1, acc);
        acc = fmaf(w22, c2, acc);
        outp[(size_t)w * 128] = siluf(acc);
        a0 = b0; a1 = b1; a2 = b2;
        b0 = c0; b1 = c1; b2 = c2;
        if (w + 2 < 64) {
            size_t off = (size_t)(w + 2) * 128;
            c0 = hm ? rm[off] : 0.f;
            c1 = r0[off];
            c2 = hp ? rp[off] : 0.f;
        } else { c0 = 0.f; c1 = 0.f; c2 = 0.f; }
    }
}

// ---- K3: x_proj (128 -> 6) — smem weights, lane=(pos,quarter), 2-step red --
// Block's 8 warps share (e,k,b); weight tile staged in smem once. Per-lane
// i-rotation (i=(ii+q)&7) makes every weight LDS 4-address conflict-free.
__global__ __launch_bounds__(256) void k3_xdbl(const float* __restrict__ xprojw)
{
    __shared__ float sw[6 * 128];
    int gw0 = blockIdx.x * 8;
    int k = (gw0 >> 9) & 3;
    int b = (gw0 >> 11) & 7;
    int e = gw0 >> 14;
    {
        const float* wsrc = xprojw + (size_t)((e * 4 + k) * 6) * 128;
        for (int i = threadIdx.x; i < 768; i += 256) sw[i] = wsrc[i];
    }
    __syncthreads();
    int w = threadIdx.x >> 5;
    int lane = threadIdx.x & 31;
    int p = lane >> 2, q = lane & 3;
    int j0 = ((gw0 + w) & 511) * 8;
    int j = j0 + p;
    int jj = (k >= 2) ? 4095 - j : j;
    int pos = (k & 1) ? ltmap(jj) : jj;
    const float* xr = g_xc + (size_t)(e * 8 + b) * 4096 * 128 + (size_t)pos * 128 + q * 32;
    const float* wq = sw + q * 32;
    float dot[6] = {0.f, 0.f, 0.f, 0.f, 0.f, 0.f};
    #pragma unroll
    for (int ii = 0; ii < 8; ii++) {
        int i = (ii + q) & 7;
        float4 x4 = *(const float4*)(xr + i * 4);
        #pragma unroll
        for (int c = 0; c < 6; c++) {
            float4 w4 = *(const float4*)(wq + c * 128 + i * 4);
            dot[c] = fmaf(x4.x, w4.x, dot[c]);
            dot[c] = fmaf(x4.y, w4.y, dot[c]);
            dot[c] = fmaf(x4.z, w4.z, dot[c]);
            dot[c] = fmaf(x4.w, w4.w, dot[c]);
        }
    }
    #pragma unroll
    for (int off = 1; off <= 2; off <<= 1) {
        #pragma unroll
        for (int c = 0; c < 6; c++)
            dot[c] += __shfl_xor_sync(0xffffffffu, dot[c], off);
    }
    if (q == 0) {
        float* rp = g_rec + (size_t)(((e * 8 + b) * 4 + k) * 4096 + j) * 8;
        *(float4*)rp       = make_float4(dot[0], dot[1], dot[2], dot[3]);
        *(float2*)(rp + 4) = make_float2(dot[4], dot[5]);
    }
}

// -- K4a: scan pass 1 — per-chunk aggregates, 2 interleaved chains/thread ----
__global__ __launch_bounds__(128) void k4a_scan_partial(
    const float* __restrict__ dtw, const float* __restrict__ dtb,
    const float* __restrict__ alogs)
{
    int blk = blockIdx.x;                 // ebk*32 + cp  (2 chunks per block)
    int cp = blk & 31;
    int ebk = blk >> 5;
    int k = ebk & 3, b = (ebk >> 2) & 7, e = ebk >> 5;
    int d = threadIdx.x;
    int kd = (e * 4 + k) * 128 + d;
    float4 w4 = *(const float4*)&dtw[kd * 4];
    float bias = dtb[kd];
    float Aval = -expf(alogs[kd]);
    const float* xb = g_xc + (size_t)(e * 8 + b) * 4096 * 128;
    const float* rec = g_rec + (size_t)((e * 8 + b) * 4 + k) * 4096 * 8;
    int j0 = cp * 2 * CLEN;
    int j1 = j0 + CLEN;
    float Ap0 = 1.f, Bp0 = 0.f, Ap1 = 1.f, Bp1 = 0.f;
    #pragma unroll 2
    for (int i = 0; i < CLEN; i++) {
        {   // chain 0
            int j = j0 + i;
            int jm = (k >= 2) ? 4095 - j : j;
            int pos = (k & 1) ? ltmap(jm) : jm;
            float4 r4 = *(const float4*)(rec + (size_t)j * 8);
            float Bs = rec[(size_t)j * 8 + 4];
            float x = xb[(size_t)pos * 128 + d];
            float zz = fmaf(w4.x, r4.x, fmaf(w4.y, r4.y, fmaf(w4.z, r4.z, fmaf(w4.w, r4.w, bias))));
            float delta = sp(zz);
            float a = __expf(delta * Aval);
            Bp0 = fmaf(Bp0, a, delta * Bs * x);
            Ap0 *= a;
        }
        {   // chain 1
            int j = j1 + i;
            int jm = (k >= 2) ? 4095 - j : j;
            int pos = (k & 1) ? ltmap(jm) : jm;
            float4 r4 = *(const float4*)(rec + (size_t)j * 8);
            float Bs = rec[(size_t)j * 8 + 4];
            float x = xb[(size_t)pos * 128 + d];
            float zz = fmaf(w4.x, r4.x, fmaf(w4.y, r4.y, fmaf(w4.z, r4.z, fmaf(w4.w, r4.w, bias))));
            float delta = sp(zz);
            float a = __expf(delta * Aval);
            Bp1 = fmaf(Bp1, a, delta * Bs * x);
            Ap1 *= a;
        }
    }
    g_aggA[(ebk * CH + cp * 2) * 128 + d] = Ap0;
    g_aggB[(ebk * CH + cp * 2) * 128 + d] = Bp0;
    g_aggA[(ebk * CH + cp * 2 + 1) * 128 + d] = Ap1;
    g_aggB[(ebk * CH + cp * 2 + 1) * 128 + d] = Bp1;
}

// ---------------- K4b: scan pass 2 — prefix across chunks -------------------
__global__ void k4b_scan_prefix()
{
    int ebk = blockIdx.x;    // 0..63
    int d = threadIdx.x;
    float h = 0.f;
    #pragma unroll
    for (int c = 0; c < CH; c++) {
        int idx = (ebk * CH + c) * 128 + d;
        float A = g_aggA[idx], Bv = g_aggB[idx];
        g_pref[idx] = h;
        h = fmaf(A, h, Bv);
    }
}

// ----- K4c: scan pass 3 — paired dirs (p, p+2), summed plane, NO smem -------
__global__ __launch_bounds__(128) void k4c_pair(
    const float* __restrict__ dtw, const float* __restrict__ dtb,
    const float* __restrict__ alogs, const float* __restrict__ dsv)
{
    int blk = blockIdx.x;                // eb*128 + p*64 + hc
    int hc = blk & 63;
    int p = (blk >> 6) & 1;
    int eb = blk >> 7;
    int e = eb >> 3;
    int d = threadIdx.x;
    int kf = p, kb = p + 2;
    int ebkf = eb * 4 + kf, ebkb = eb * 4 + kb;
    int kdf = (e * 4 + kf) * 128 + d;
    int kdb = (e * 4 + kb) * 128 + d;
    float4 wf = *(const float4*)&dtw[kdf * 4];
    float4 wb = *(const float4*)&dtw[kdb * 4];
    float biasf = dtb[kdf], biasb = dtb[kdb];
    float Avf = -expf(alogs[kdf]), Avb = -expf(alogs[kdb]);
    float Dvf = dsv[kdf], Dvb = dsv[kdb];
    const float* xb = g_xc + (size_t)eb * 4096 * 128;
    const float* recf = g_rec + (size_t)ebkf * 4096 * 8;
    const float* recb = g_rec + (size_t)ebkb * 4096 * 8;
    float* outp = (p ? g_ysB : g_ysA) + ((size_t)eb * 4096 + hc * CLEN) * 128 + d;
    // dir p+2, its chunk (63-hc), time-forward = i descending; write y2
    float hb = g_pref[(ebkb * CH + (CH - 1 - hc)) * 128 + d];
    #pragma unroll 4
    for (int i = CLEN - 1; i >= 0; i--) {
        int jj = hc * CLEN + i;
        int pos = p ? ltmap(jj) : jj;
        int jb = 4095 - jj;
        const float* rp = recb + (size_t)jb * 8;
        float4 r4 = *(const float4*)rp;
        float Bs = rp[4], Cs = rp[5];
        float x = xb[(size_t)pos * 128 + d];
        float zz = fmaf(wb.x, r4.x, fmaf(wb.y, r4.y, fmaf(wb.z, r4.z, fmaf(wb.w, r4.w, biasb))));
        float delta = sp(zz);
        float a = __expf(delta * Avb);
        hb = fmaf(a, hb, delta * Bs * x);
        outp[(size_t)i * 128] = fmaf(hb, Cs, Dvb * x);
    }
    // dir p, chunk hc, forward; add y1
    float hf = g_pref[(ebkf * CH + hc) * 128 + d];
    #pragma unroll 4
    for (int i = 0; i < CLEN; i++) {
        int jj = hc * CLEN + i;
        int pos = p ? ltmap(jj) : jj;
        const float* rp = recf + (size_t)jj * 8;
        float4 r4 = *(const float4*)rp;
        float Bs = rp[4], Cs = rp[5];
        float x = xb[(size_t)pos * 128 + d];
        float zz = fmaf(wf.x, r4.x, fmaf(wf.y, r4.y, fmaf(wf.z, r4.z, fmaf(wf.w, r4.w, biasf))));
        float delta = sp(zz);
        float a = __expf(delta * Avf);
        hf = fmaf(a, hf, delta * Bs * x);
        float y1 = fmaf(hf, Cs, Dvf * x);
        outp[(size_t)i * 128] += y1;
    }
}

// -- K6: sum 2 planes + LN*z + out_proj (128->64) via tensor cores + resid ---
__global__ __launch_bounds__(128) void k6_mma(
    const float* __restrict__ mag, const float* __restrict__ phase,
    const float* __restrict__ onw, const float* __restrict__ onb)
{
    __shared__ float syf[32 * 128];
    __shared__ __nv_bfloat16 sAh[32 * 136];
    __shared__ __nv_bfloat16 sAl[32 * 136];
    __shared__ float smu[32], srs[32];
    int row0 = blockIdx.x * 32;
    int e = row0 >> 15;
    int ebbase = row0 & ~4095;       // eb*4096
    int t = threadIdx.x;
    int lane = t & 31, wid = t >> 5;
    int group = lane >> 2, tig = lane & 3;
    {
        int r = t >> 2, c0 = (t & 3) * 32;
        int s = (row0 & 4095) + r;
        int jj = ltmap(s);
        const float* pA = &g_ysA[(size_t)(row0 + r) * 128 + c0];
        const float* pB = &g_ysB[(size_t)(ebbase + jj) * 128 + c0];
        #pragma unroll
        for (int i = 0; i < 8; i++) {
            float4 vA = *(const float4*)&pA[4 * i];
            float4 vB = *(const float4*)&pB[4 * i];
            syf[r * 128 + c0 + 4*i + 0] = vA.x + vB.x;
            syf[r * 128 + c0 + 4*i + 1] = vA.y + vB.y;
            syf[r * 128 + c0 + 4*i + 2] = vA.z + vB.z;
            syf[r * 128 + c0 + 4*i + 3] = vA.w + vB.w;
        }
    }
    __syncthreads();
    if (t < 32) {
        float s = 0.f, s2 = 0.f;
        #pragma unroll 8
        for (int i = 0; i < 128; i++) { float v = syf[t * 128 + i]; s += v; s2 += v * v; }
        float mu = s * (1.f / 128.f);
        smu[t] = mu;
        srs[t] = rsqrtf(fmaxf(s2 * (1.f / 128.f) - mu * mu, 0.f) + 1e-5f);
    }
    __syncthreads();
    #pragma unroll
    for (int idx = 0; idx < 32; idx++) {
        int q = idx * 128 + t;
        int rr = q >> 7, cc = q & 127;
        float v = (syf[rr * 128 + cc] - smu[rr]) * srs[rr] * onw[e * 128 + cc] + onb[e * 128 + cc];
        v *= g_z[(size_t)(row0 + rr) * 128 + cc];
        __nv_bfloat16 h = __float2bfloat16(v);
        sAh[rr * 136 + cc] = h;
        sAl[rr * 136 + cc] = __float2bfloat16(v - __bfloat162float(h));
    }
    __syncthreads();
    // GEMM C[32,64] = A[32,128] * Wop^T
    int mt = wid & 1;
    int nb2 = (wid >> 1) * 32;
    float c2[4][4];
    #pragma unroll
    for (int i = 0; i < 4; i++)
        { c2[i][0] = 0.f; c2[i][1] = 0.f; c2[i][2] = 0.f; c2[i][3] = 0.f; }
    #pragma unroll
    for (int ks = 0; ks < 8; ks++) {
        int ar = mt * 16 + group;
        int kk = ks * 16 + tig * 2;
        unsigned ah0 = *(const unsigned*)(sAh + ar * 136 + kk);
        unsigned ah1 = *(const unsigned*)(sAh + (ar + 8) * 136 + kk);
        unsigned ah2 = *(const unsigned*)(sAh + ar * 136 + kk + 8);
        unsigned ah3 = *(const unsigned*)(sAh + (ar + 8) * 136 + kk + 8);
        unsigned al0 = *(const unsigned*)(sAl + ar * 136 + kk);
        unsigned al1 = *(const unsigned*)(sAl + (ar + 8) * 136 + kk);
        unsigned al2 = *(const unsigned*)(sAl + ar * 136 + kk + 8);
        unsigned al3 = *(const unsigned*)(sAl + (ar + 8) * 136 + kk + 8);
        const uint2* wbase = g_wop + (size_t)(e * 64 + nb2 + group) * 64 + ks * 8 + tig;
        #pragma unroll
        for (int nt = 0; nt < 4; nt++) {
            const uint2* wp = wbase + nt * 512;   // n += 8 -> +8*64 pairs
            uint2 v0 = wp[0];
            uint2 v1 = wp[4];
            mma16816(c2[nt], ah0, ah1, ah2, ah3, v0.x, v1.x);
            mma16816(c2[nt], ah0, ah1, ah2, ah3, v0.y, v1.y);
            mma16816(c2[nt], al0, al1, al2, al3, v0.x, v1.x);
        }
    }
    const float* xin = e ? phase : mag;
    int rl0 = row0 & 32767;
    #pragma unroll
    for (int nt = 0; nt < 4; nt++) {
        int colb = nb2 + nt * 8 + tig * 2;
        int r0 = mt * 16 + group;
        float2 x0 = *(const float2*)&xin[(rl0 + r0) * 64 + colb];
        float2 x1 = *(const float2*)&xin[(rl0 + r0 + 8) * 64 + colb];
        *(float2*)&g_xres[(row0 + r0) * 64 + colb] =
            make_float2(c2[nt][0] + x0.x, c2[nt][1] + x0.y);
        *(float2*)&g_xres[(row0 + r0 + 8) * 64 + colb] =
            make_float2(c2[nt][2] + x1.x, c2[nt][3] + x1.y);
    }
}

// -------- K7: LN + fc1 + gelu + fc2 + residual — tensor-core bf16 split -----
__global__ __launch_bounds__(128) void k7_mlp_mma(
    const float* __restrict__ n2w, const float* __restrict__ n2b,
    const float* __restrict__ f1b, const float* __restrict__ f2b)
{
    __shared__ __align__(16) unsigned char smraw[43264];
    float* sxf = (float*)smraw;                              // 32x64 f32 (early)
    __nv_bfloat16* sHh = (__nv_bfloat16*)smraw;              // 32x264
    __nv_bfloat16* sHl = (__nv_bfloat16*)(smraw + 16896);
    __nv_bfloat16* sAh = (__nv_bfloat16*)(smraw + 33792);    // 32x72
    __nv_bfloat16* sAl = (__nv_bfloat16*)(smraw + 38400);
    float* smu = (float*)(smraw + 43008);
    float* srs = (float*)(smraw + 43136);

    int row0 = blockIdx.x * 32;
    int e = row0 >> 15;
    int t = threadIdx.x;
    int lane = t & 31, wid = t >> 5;
    int group = lane >> 2, tig = lane & 3;

    {
        int r = t >> 2, c0 = (t & 3) * 16;
        #pragma unroll
        for (int i = 0; i < 4; i++) {
            float4 v = *(const float4*)&g_xres[(row0 + r) * 64 + c0 + 4 * i];
            sxf[r * 64 + c0 + 4*i + 0] = v.x; sxf[r * 64 + c0 + 4*i + 1] = v.y;
            sxf[r * 64 + c0 + 4*i + 2] = v.z; sxf[r * 64 + c0 + 4*i + 3] = v.w;
        }
    }
    __syncthreads();
    if (t < 32) {
        float s = 0.f, s2 = 0.f;
        #pragma unroll
        for (int i = 0; i < 64; i++) { float v = sxf[t * 64 + i]; s += v; s2 += v * v; }
        float mu = s * (1.f / 64.f);
        smu[t] = mu;
        srs[t] = rsqrtf(fmaxf(s2 * (1.f / 64.f) - mu * mu, 0.f) + 1e-5f);
    }
    __syncthreads();
    #pragma unroll
    for (int idx = 0; idx < 16; idx++) {
        int q = idx * 128 + t;           // 0..2047
        int rr = q >> 6, cc = q & 63;
        float v = (sxf[rr * 64 + cc] - smu[rr]) * srs[rr] * n2w[e * 64 + cc] + n2b[e * 64 + cc];
        __nv_bfloat16 h = __float2bfloat16(v);
        sAh[rr * 72 + cc] = h;
        sAl[rr * 72 + cc] = __float2bfloat16(v - __bfloat162float(h));
    }
    __syncthreads();

    // fc1
    int mt = wid & 1;
    int nb = (wid >> 1) * 128;
    float c1[16][4];
    #pragma unroll
    for (int i = 0; i < 16; i++)
        { c1[i][0] = 0.f; c1[i][1] = 0.f; c1[i][2] = 0.f; c1[i][3] = 0.f; }
    #pragma unroll
    for (int ks = 0; ks < 4; ks++) {
        int ar = mt * 16 + group;
        int kk = ks * 16 + tig * 2;
        unsigned ah0 = *(const unsigned*)(sAh + ar * 72 + kk);
        unsigned ah1 = *(const unsigned*)(sAh + (ar + 8) * 72 + kk);
        unsigned ah2 = *(const unsigned*)(sAh + ar * 72 + kk + 8);
        unsigned ah3 = *(const unsigned*)(sAh + (ar + 8) * 72 + kk + 8);
        unsigned al0 = *(const unsigned*)(sAl + ar * 72 + kk);
        unsigned al1 = *(const unsigned*)(sAl + (ar + 8) * 72 + kk);
        unsigned al2 = *(const unsigned*)(sAl + ar * 72 + kk + 8);
        unsigned al3 = *(const unsigned*)(sAl + (ar + 8) * 72 + kk + 8);
        const uint2* wbase = g_w1p + (size_t)(e * 256 + nb + group) * 32 + ks * 8 + tig;
        #pragma unroll
        for (int nt = 0; nt < 16; nt++) {
            const uint2* wp = wbase + nt * 256;
            uint2 v0 = wp[0];
            uint2 v1 = wp[4];
            mma16816(c1[nt], ah0, ah1, ah2, ah3, v0.x, v1.x);
            mma16816(c1[nt], ah0, ah1, ah2, ah3, v0.y, v1.y);
            mma16816(c1[nt], al0, al1, al2, al3, v0.x, v1.x);
        }
    }
    #pragma unroll
    for (int nt = 0; nt < 16; nt++) {
        int colb = nb + nt * 8 + tig * 2;
        float2 b1 = *(const float2*)&f1b[e * 256 + colb];
        int r0 = mt * 16 + group;
        float g00 = geluf(c1[nt][0] + b1.x);
        float g01 = geluf(c1[nt][1] + b1.y);
        float g10 = geluf(c1[nt][2] + b1.x);
        float g11 = geluf(c1[nt][3] + b1.y);
        __nv_bfloat16 h;
        h = __float2bfloat16(g00); sHh[r0 * 264 + colb]           = h; sHl[r0 * 264 + colb]           = __float2bfloat16(g00 - __bfloat162float(h));
        h = __float2bfloat16(g01); sHh[r0 * 264 + colb + 1]       = h; sHl[r0 * 264 + colb + 1]       = __float2bfloat16(g01 - __bfloat162float(h));
        h = __float2bfloat16(g10); sHh[(r0 + 8) * 264 + colb]     = h; sHl[(r0 + 8) * 264 + colb]     = __float2bfloat16(g10 - __bfloat162float(h));
        h = __float2bfloat16(g11); sHh[(r0 + 8) * 264 + colb + 1] = h; sHl[(r0 + 8) * 264 + colb + 1] = __float2bfloat16(g11 - __bfloat162float(h));
    }
    __syncthreads();

    // fc2
    int nb2 = (wid >> 1) * 32;
    float c2[4][4];
    #pragma unroll
    for (int i = 0; i < 4; i++)
        { c2[i][0] = 0.f; c2[i][1] = 0.f; c2[i][2] = 0.f; c2[i][3] = 0.f; }
    #pragma unroll 4
    for (int ks = 0; ks < 16; ks++) {
        int ar = mt * 16 + group;
        int kk = ks * 16 + tig * 2;
        unsigned ah0 = *(const unsigned*)(sHh + ar * 264 + kk);
        unsigned ah1 = *(const unsigned*)(sHh + (ar + 8) * 264 + kk);
        unsigned ah2 = *(const unsigned*)(sHh + ar * 264 + kk + 8);
        unsigned ah3 = *(const unsigned*)(sHh + (ar + 8) * 264 + kk + 8);
        unsigned al0 = *(const unsigned*)(sHl + ar * 264 + kk);
        unsigned al1 = *(const unsigned*)(sHl + (ar + 8) * 264 + kk);
        unsigned al2 = *(const unsigned*)(sHl + ar * 264 + kk + 8);
        unsigned al3 = *(const unsigned*)(sHl + (ar + 8) * 264 + kk + 8);
        const uint2* wbase = g_w2p + (size_t)(e * 64 + nb2 + group) * 128 + ks * 8 + tig;
        #pragma unroll
        for (int nt = 0; nt < 4; nt++) {
            const uint2* wp = wbase + nt * 1024;
            uint2 v0 = wp[0];
            uint2 v1 = wp[4];
            mma16816(c2[nt], ah0, ah1, ah2, ah3, v0.x, v1.x);
            mma16816(c2[nt], ah0, ah1, ah2, ah3, v0.y, v1.y);
            mma16816(c2[nt], al0, al1, al2, al3, v0.x, v1.x);
        }
    }
    #pragma unroll
    for (int nt = 0; nt < 4; nt++) {
        int colb = nb2 + nt * 8 + tig * 2;
        float2 b2 = *(const float2*)&f2b[e * 64 + colb];
        int r0g = row0 + mt * 16 + group;
        float2 x0 = *(const float2*)&g_xres[r0g * 64 + colb];
        float2 x1 = *(const float2*)&g_xres[(r0g + 8) * 64 + colb];
        float2 o0 = make_float2(x0.x + c2[nt][0] + b2.x, x0.y + c2[nt][1] + b2.y);
        float2 o1 = make_float2(x1.x + c2[nt][2] + b2.x, x1.y + c2[nt][3] + b2.y);
        *(float2*)&g_mlp[r0g * 64 + colb] = o0;
        *(float2*)&g_mlp[(r0g + 8) * 64 + colb] = o1;
    }
}

// ---------------- K8: sum streams, duplicate output (float4) ----------------
__global__ void k8_final(float* __restrict__ out)
{
    int i = blockIdx.x * 256 + threadIdx.x;   // 0..524287 (float4 units)
    float4 a = *(const float4*)&g_mlp[4 * i];
    float4 b = *(const float4*)&g_mlp[4 * i + 2097152];
    float4 s = make_float4(a.x + b.x, a.y + b.y, a.z + b.z, a.w + b.w);
    *(float4*)&out[4 * i] = s;
    *(float4*)&out[4 * i + 2097152] = s;
}

// ---------------- launch ----------------------------------------------------
extern "C" void kernel_launch(void* const* d_in, const int* in_sizes, int n_in,
                              void* d_out, int out_size)
{
    const float* mag   = (const float*)d_in[0];
    const float* phase = (const float*)d_in[1];
    const float* n1w   = (const float*)d_in[2];
    const float* n1b   = (const float*)d_in[3];
    const float* ipw   = (const float*)d_in[4];
    const float* cvw   = (const float*)d_in[5];
    const float* xpw   = (const float*)d_in[6];
    const float* dtw   = (const float*)d_in[7];
    const float* dtb   = (const float*)d_in[8];
    const float* alg   = (const float*)d_in[9];
    const float* dsv   = (const float*)d_in[10];
    const float* onw   = (const float*)d_in[11];
    const float* onb   = (const float*)d_in[12];
    const float* opw   = (const float*)d_in[13];
    const float* n2w   = (const float*)d_in[14];
    const float* n2b   = (const float*)d_in[15];
    const float* f1w   = (const float*)d_in[16];
    const float* f1b   = (const float*)d_in[17];
    const float* f2w   = (const float*)d_in[18];
    const float* f2b   = (const float*)d_in[19];

    k0_prep<<<224, 256>>>(f1w, f2w, ipw, opw);
    k1_mma<<<2048, 128>>>(mag, phase, n1w, n1b);
    k2_conv<<<1024, 128>>>(cvw);
    k3_xdbl<<<4096, 256>>>(xpw);
    k4a_scan_partial<<<2048, 128>>>(dtw, dtb, alg);
    k4b_scan_prefix<<<64, 128>>>();
    k4c_pair<<<2048, 128>>>(dtw, dtb, alg, dsv);
    k6_mma<<<2048, 128>>>(mag, phase, onw, onb);
    k7_mlp_mma<<<2048, 128>>>(n2w, n2b, f1b, f2b);
    k8_final<<<2048, 256>>>((float*)d_out);
}

// round 17
// speedup vs baseline: 1.2331x; 1.0380x over previous
#include <cuda_runtime.h>
#include <cuda_bf16.h>
#include <math.h>

// Problem constants
// E=2 streams, B=8, H=W=64, C=64, DI=128, L=4096, K=4 dirs, R=4, N=1
#define EB 16            // E*B
#define L_ 4096
#define DI_ 128
#define C_ 64
#define CH 64            // scan chunks per sequence
#define CLEN 64          // chunk length (CH*CLEN = L)

// ---------------- scratch (static __device__, no allocation) ----------------
__device__ float g_xcpre[EB * L_ * DI_];     // pre-conv x branch [eb][s][d]
__device__ float g_z    [EB * L_ * DI_];     // silu(z)           [eb][s][d]
__device__ float g_xc   [EB * L_ * DI_];     // conv+silu output  [eb][s][d]
__device__ float g_rec  [EB * 4 * L_ * 8];   // per (eb,k,j): dt0..3, Bs, Cs, pad2
__device__ float g_aggA [64 * CH * DI_];     // chunk aggregate A
__device__ float g_aggB [64 * CH * DI_];     // chunk aggregate B
__device__ float g_pref [64 * CH * DI_];     // incoming prefix per chunk
__device__ float g_ysA  [EB * L_ * DI_];     // y(dir0)+y(dir2), spatial order
__device__ float g_ysB  [EB * L_ * DI_];     // y(dir1)+y(dir3), j-order
__device__ float g_xres [EB * L_ * C_];      // residual after attention part
__device__ float g_mlp  [EB * L_ * C_];      // per-stream final output
// packed bf16 hi/lo weights (built by k0_prep each call)
__device__ uint2 g_w1p[2 * 256 * 32];        // f1w pairs: [(e,n)][k/2] -> (hi2, lo2)
__device__ uint2 g_w2p[2 * 64 * 128];        // f2w pairs
__device__ uint2 g_wip[2 * 256 * 32];        // in_proj pairs
__device__ uint2 g_wop[2 * 64 * 64];         // out_proj pairs
__device__ uint2 g_wxp[2 * 4 * 8 * 64];      // x_proj pairs, cols padded 6->8

__device__ __forceinline__ int ltmap(int j) { return ((j & 63) << 6) | (j >> 6); }

__device__ __forceinline__ float siluf(float v) {
    return v / (1.f + __expf(-v));
}
__device__ __forceinline__ float sp(float x) {   // softplus, stable + fast
    return fmaxf(x, 0.f) + __logf(1.f + __expf(-fabsf(x)));
}
__device__ __forceinline__ float geluf(float v) {
    return 0.5f * v * (1.f + erff(v * 0.70710678118654752f));
}

// ---------------- bf16 mma helpers ------------------------------------------
__device__ __forceinline__ void mma16816(float c[4],
    unsigned a0, unsigned a1, unsigned a2, unsigned a3,
    unsigned b0, unsigned b1)
{
    asm("mma.sync.aligned.m16n8k16.row.col.f32.bf16.bf16.f32 "
        "{%0,%1,%2,%3}, {%4,%5,%6,%7}, {%8,%9}, {%0,%1,%2,%3};"
        : "+f"(c[0]), "+f"(c[1]), "+f"(c[2]), "+f"(c[3])
        : "r"(a0), "r"(a1), "r"(a2), "r"(a3), "r"(b0), "r"(b1));
}
__device__ __forceinline__ unsigned pkbf(float a, float b) {
    unsigned short ua = __bfloat16_as_ushort(__float2bfloat16(a));
    unsigned short ub = __bfloat16_as_ushort(__float2bfloat16(b));
    return (unsigned)ua | ((unsigned)ub << 16);
}

// ------------- K0: split GEMM weights to packed bf16 hi/lo ------------------
__global__ void k0_prep(const float* __restrict__ f1w, const float* __restrict__ f2w,
                        const float* __restrict__ ipw, const float* __restrict__ opw,
                        const float* __restrict__ xpw)
{
    int i = blockIdx.x * 256 + threadIdx.x;     // 0..61439
    float a0, a1; uint2* dst; int p;
    if (i < 57344) {
        const float* src;
        if (i < 16384)      { src = f1w; dst = g_w1p; p = i; }
        else if (i < 32768) { src = f2w; dst = g_w2p; p = i - 16384; }
        else if (i < 49152) { src = ipw; dst = g_wip; p = i - 32768; }
        else                { src = opw; dst = g_wop; p = i - 49152; }
        a0 = src[2 * p]; a1 = src[2 * p + 1];
    } else {
        int idx = i - 57344;                     // 0..4095
        int ek = idx >> 9;                       // e*4+k
        int c  = (idx >> 6) & 7;
        p = idx;
        dst = g_wxp;
        if (c < 6) {
            int kp = idx & 63;
            a0 = xpw[(ek * 6 + c) * 128 + 2 * kp];
            a1 = xpw[(ek * 6 + c) * 128 + 2 * kp + 1];
        } else { a0 = 0.f; a1 = 0.f; }
    }
    __nv_bfloat16 h0 = __float2bfloat16(a0), h1 = __float2bfloat16(a1);
    float l0 = a0 - __bfloat162float(h0);
    float l1 = a1 - __bfloat162float(h1);
    unsigned hi = (unsigned)__bfloat16_as_ushort(h0) | ((unsigned)__bfloat16_as_ushort(h1) << 16);
    unsigned lo = pkbf(l0, l1);
    dst[p] = make_uint2(hi, lo);
}

// ------ K1: LN + in_proj (64->256) via tensor cores, split, silu(z) ---------
__global__ __launch_bounds__(128) void k1_mma(
    const float* __restrict__ mag, const float* __restrict__ phase,
    const float* __restrict__ n1w, const float* __restrict__ n1b)
{
    __shared__ float sxf[32 * 64];
    __shared__ __nv_bfloat16 sAh[32 * 72];
    __shared__ __nv_bfloat16 sAl[32 * 72];
    __shared__ float smu[32], srs[32];
    int row0 = blockIdx.x * 32;
    int e = row0 >> 15;
    const float* xin = e ? phase : mag;
    int rloc0 = row0 & 32767;
    int t = threadIdx.x;
    int lane = t & 31, wid = t >> 5;
    int group = lane >> 2, tig = lane & 3;
    {
        int r = t >> 2, c0 = (t & 3) * 16;
        #pragma unroll
        for (int i = 0; i < 4; i++) {
            float4 v = *(const float4*)&xin[(rloc0 + r) * 64 + c0 + 4 * i];
            sxf[r * 64 + c0 + 4*i + 0] = v.x; sxf[r * 64 + c0 + 4*i + 1] = v.y;
            sxf[r * 64 + c0 + 4*i + 2] = v.z; sxf[r * 64 + c0 + 4*i + 3] = v.w;
        }
    }
    __syncthreads();
    if (t < 32) {
        float s = 0.f, s2 = 0.f;
        #pragma unroll
        for (int i = 0; i < 64; i++) { float v = sxf[t * 64 + i]; s += v; s2 += v * v; }
        float mu = s * (1.f / 64.f);
        smu[t] = mu;
        srs[t] = rsqrtf(fmaxf(s2 * (1.f / 64.f) - mu * mu, 0.f) + 1e-5f);
    }
    __syncthreads();
    #pragma unroll
    for (int idx = 0; idx < 16; idx++) {
        int q = idx * 128 + t;
        int rr = q >> 6, cc = q & 63;
        float v = (sxf[rr * 64 + cc] - smu[rr]) * srs[rr] * n1w[e * 64 + cc] + n1b[e * 64 + cc];
        __nv_bfloat16 h = __float2bfloat16(v);
        sAh[rr * 72 + cc] = h;
        sAl[rr * 72 + cc] = __float2bfloat16(v - __bfloat162float(h));
    }
    __syncthreads();
    // GEMM C[32,256] = A[32,64] * Wip^T  (warps: mt = row-tile, nb = col-half)
    int mt = wid & 1;
    int nb = (wid >> 1) * 128;
    float c1[16][4];
    #pragma unroll
    for (int i = 0; i < 16; i++)
        { c1[i][0] = 0.f; c1[i][1] = 0.f; c1[i][2] = 0.f; c1[i][3] = 0.f; }
    #pragma unroll
    for (int ks = 0; ks < 4; ks++) {
        int ar = mt * 16 + group;
        int kk = ks * 16 + tig * 2;
        unsigned ah0 = *(const unsigned*)(sAh + ar * 72 + kk);
        unsigned ah1 = *(const unsigned*)(sAh + (ar + 8) * 72 + kk);
        unsigned ah2 = *(const unsigned*)(sAh + ar * 72 + kk + 8);
        unsigned ah3 = *(const unsigned*)(sAh + (ar + 8) * 72 + kk + 8);
        unsigned al0 = *(const unsigned*)(sAl + ar * 72 + kk);
        unsigned al1 = *(const unsigned*)(sAl + (ar + 8) * 72 + kk);
        unsigned al2 = *(const unsigned*)(sAl + ar * 72 + kk + 8);
        unsigned al3 = *(const unsigned*)(sAl + (ar + 8) * 72 + kk + 8);
        const uint2* wbase = g_wip + (size_t)(e * 256 + nb + group) * 32 + ks * 8 + tig;
        #pragma unroll
        for (int nt = 0; nt < 16; nt++) {
            const uint2* wp = wbase + nt * 256;
            uint2 v0 = wp[0];
            uint2 v1 = wp[4];
            mma16816(c1[nt], ah0, ah1, ah2, ah3, v0.x, v1.x);
            mma16816(c1[nt], ah0, ah1, ah2, ah3, v0.y, v1.y);
            mma16816(c1[nt], al0, al1, al2, al3, v0.x, v1.x);
        }
    }
    // store: cols <128 -> g_xcpre ; cols >=128 -> silu -> g_z (uniform per warp)
    if (nb == 0) {
        #pragma unroll
        for (int nt = 0; nt < 16; nt++) {
            int colb = nt * 8 + tig * 2;
            int r0 = row0 + mt * 16 + group;
            *(float2*)&g_xcpre[r0 * 128 + colb]       = make_float2(c1[nt][0], c1[nt][1]);
            *(float2*)&g_xcpre[(r0 + 8) * 128 + colb] = make_float2(c1[nt][2], c1[nt][3]);
        }
    } else {
        #pragma unroll
        for (int nt = 0; nt < 16; nt++) {
            int colb = nt * 8 + tig * 2;
            int r0 = row0 + mt * 16 + group;
            *(float2*)&g_z[r0 * 128 + colb]       = make_float2(siluf(c1[nt][0]), siluf(c1[nt][1]));
            *(float2*)&g_z[(r0 + 8) * 128 + colb] = make_float2(siluf(c1[nt][2]), siluf(c1[nt][3]));
        }
    }
}

// ------ K2: depthwise 3x3 conv + silu — rolling window along w --------------
__global__ __launch_bounds__(128) void k2_conv(const float* __restrict__ cw)
{
    int blk = blockIdx.x;            // eb*64 + h
    int h = blk & 63;
    int eb = blk >> 6;
    int e = eb >> 3;
    int d = threadIdx.x;
    const float* base = g_xcpre + (size_t)eb * 4096 * 128 + d;
    float* outp = g_xc + (size_t)(eb * 4096 + h * 64) * 128 + d;
    const float* wk = &cw[(e * 128 + d) * 9];
    float w00 = wk[0], w01 = wk[1], w02 = wk[2];
    float w10 = wk[3], w11 = wk[4], w12 = wk[5];
    float w20 = wk[6], w21 = wk[7], w22 = wk[8];
    bool hm = (h > 0), hp = (h < 63);
    const float* rm = base + (size_t)((h - 1) * 64) * 128;
    const float* r0 = base + (size_t)(h * 64) * 128;
    const float* rp = base + (size_t)((h + 1) * 64) * 128;
    float a0 = 0.f, a1 = 0.f, a2 = 0.f;                 // col w-1
    float b0 = hm ? rm[0] : 0.f, b1 = r0[0], b2 = hp ? rp[0] : 0.f;   // col w
    float c0 = hm ? rm[128] : 0.f, c1 = r0[128], c2 = hp ? rp[128] : 0.f; // col w+1
    #pragma unroll 4
    for (int w = 0; w < 64; w++) {
        float acc = w00 * a0;
        acc = fmaf(w10, a1, acc);
        acc = fmaf(w20, a2, acc);
        acc = fmaf(w01, b0, acc);
        acc = fmaf(w11, b1, acc);
        acc = fmaf(w21, b2, acc);
        acc = fmaf(w02, c0, acc);
        acc = fmaf(w12, c1, acc);
        acc = fmaf(w22, c2, acc);
        outp[(size_t)w * 128] = siluf(acc);
        a0 = b0; a1 = b1; a2 = b2;
        b0 = c0; b1 = c1; b2 = c2;
        if (w + 2 < 64) {
            size_t off = (size_t)(w + 2) * 128;
            c0 = hm ? rm[off] : 0.f;
            c1 = r0[off];
            c2 = hp ? rp[off] : 0.f;
        } else { c0 = 0.f; c1 = 0.f; c2 = 0.f; }
    }
}

// ---- K3: x_proj (128->6) x 4 dirs — spatial-order fused bf16-split MMA -----
// Block = 64 contiguous x rows; ONE stage+split serves all 4 directions.
// Warp w: M-tile mt=w&3 (16 rows), dirs {2*(w>>2), 2*(w>>2)+1}. Fragment and
// weight indexing identical to validated round-12 kernel; outputs scatter to
// g_rec rows via the per-direction index maps.
__global__ __launch_bounds__(256) void k3_mma()
{
    __shared__ __nv_bfloat16 sXh[64 * 136];
    __shared__ __nv_bfloat16 sXl[64 * 136];
    int blk = blockIdx.x;            // eb*64 + st
    int st = blk & 63;
    int eb = blk >> 6;
    int e = eb >> 3;
    int s0 = st * 64;
    const float* xb = g_xc + (size_t)eb * 4096 * 128 + (size_t)s0 * 128;
    int t = threadIdx.x;
    {
        int r = t >> 2, cq = (t & 3) * 32;
        const float4* src = (const float4*)(xb + (size_t)r * 128 + cq);
        unsigned* dh = (unsigned*)(sXh + r * 136 + cq);
        unsigned* dl = (unsigned*)(sXl + r * 136 + cq);
        #pragma unroll
        for (int i = 0; i < 8; i++) {
            float4 v = src[i];
            __nv_bfloat16 hx = __float2bfloat16(v.x);
            __nv_bfloat16 hy = __float2bfloat16(v.y);
            __nv_bfloat16 hz = __float2bfloat16(v.z);
            __nv_bfloat16 hw = __float2bfloat16(v.w);
            dh[2*i]   = (unsigned)__bfloat16_as_ushort(hx) | ((unsigned)__bfloat16_as_ushort(hy) << 16);
            dh[2*i+1] = (unsigned)__bfloat16_as_ushort(hz) | ((unsigned)__bfloat16_as_ushort(hw) << 16);
            dl[2*i]   = pkbf(v.x - __bfloat162float(hx), v.y - __bfloat162float(hy));
            dl[2*i+1] = pkbf(v.z - __bfloat162float(hz), v.w - __bfloat162float(hw));
        }
    }
    __syncthreads();
    int lane = t & 31, wid = t >> 5;
    int group = lane >> 2, tig = lane & 3;
    int mt = wid & 3;
    int half = wid >> 2;
    int ar = mt * 16 + group;
    float ca[4] = {0.f, 0.f, 0.f, 0.f};
    float cb[4] = {0.f, 0.f, 0.f, 0.f};
    #pragma unroll
    for (int ks = 0; ks < 8; ks++) {
        int kk = ks * 16 + tig * 2;
        unsigned ah0 = *(const unsigned*)(sXh + ar * 136 + kk);
        unsigned ah1 = *(const unsigned*)(sXh + (ar + 8) * 136 + kk);
        unsigned ah2 = *(const unsigned*)(sXh + ar * 136 + kk + 8);
        unsigned ah3 = *(const unsigned*)(sXh + (ar + 8) * 136 + kk + 8);
        unsigned al0 = *(const unsigned*)(sXl + ar * 136 + kk);
        unsigned al1 = *(const unsigned*)(sXl + (ar + 8) * 136 + kk);
        unsigned al2 = *(const unsigned*)(sXl + ar * 136 + kk + 8);
        unsigned al3 = *(const unsigned*)(sXl + (ar + 8) * 136 + kk + 8);
        {
            int kd = half * 2;
            const uint2* wp = g_wxp + (size_t)((e * 4 + kd) * 8 + group) * 64 + ks * 8 + tig;
            uint2 v0 = wp[0], v1 = wp[4];
            mma16816(ca, ah0, ah1, ah2, ah3, v0.x, v1.x);
            mma16816(ca, ah0, ah1, ah2, ah3, v0.y, v1.y);
            mma16816(ca, al0, al1, al2, al3, v0.x, v1.x);
        }
        {
            int kd = half * 2 + 1;
            const uint2* wp = g_wxp + (size_t)((e * 4 + kd) * 8 + group) * 64 + ks * 8 + tig;
            uint2 v0 = wp[0], v1 = wp[4];
            mma16816(cb, ah0, ah1, ah2, ah3, v0.x, v1.x);
            mma16816(cb, ah0, ah1, ah2, ah3, v0.y, v1.y);
            mma16816(cb, al0, al1, al2, al3, v0.x, v1.x);
        }
    }
    // scatter: row s -> rec row j(k,s)
    #pragma unroll
    for (int n2 = 0; n2 < 2; n2++) {
        int kd = half * 2 + n2;
        const float* cc = n2 ? cb : ca;
        float* rb = g_rec + (size_t)(eb * 4 + kd) * 4096 * 8;
        int s_a = s0 + ar;
        int s_b = s_a + 8;
        int jja = (kd & 1) ? ltmap(s_a) : s_a;
        int jjb = (kd & 1) ? ltmap(s_b) : s_b;
        int ja = (kd >= 2) ? 4095 - jja : jja;
        int jb = (kd >= 2) ? 4095 - jjb : jjb;
        *(float2*)&rb[(size_t)ja * 8 + tig * 2] = make_float2(cc[0], cc[1]);
        *(float2*)&rb[(size_t)jb * 8 + tig * 2] = make_float2(cc[2], cc[3]);
    }
}

// -- K4a: scan pass 1 — per-chunk aggregates, 2 interleaved chains/thread ----
__global__ __launch_bounds__(128) void k4a_scan_partial(
    const float* __restrict__ dtw, const float* __restrict__ dtb,
    const float* __restrict__ alogs)
{
    int blk = blockIdx.x;                 // ebk*32 + cp  (2 chunks per block)
    int cp = blk & 31;
    int ebk = blk >> 5;
    int k = ebk & 3, b = (ebk >> 2) & 7, e = ebk >> 5;
    int d = threadIdx.x;
    int kd = (e * 4 + k) * 128 + d;
    float4 w4 = *(const float4*)&dtw[kd * 4];
    float bias = dtb[kd];
    float Aval = -expf(alogs[kd]);
    const float* xb = g_xc + (size_t)(e * 8 + b) * 4096 * 128;
    const float* rec = g_rec + (size_t)((e * 8 + b) * 4 + k) * 4096 * 8;
    int j0 = cp * 2 * CLEN;
    int j1 = j0 + CLEN;
    float Ap0 = 1.f, Bp0 = 0.f, Ap1 = 1.f, Bp1 = 0.f;
    #pragma unroll 2
    for (int i = 0; i < CLEN; i++) {
        {   // chain 0
            int j = j0 + i;
            int jm = (k >= 2) ? 4095 - j : j;
            int pos = (k & 1) ? ltmap(jm) : jm;
            float4 r4 = *(const float4*)(rec + (size_t)j * 8);
            float Bs = rec[(size_t)j * 8 + 4];
            float x = xb[(size_t)pos * 128 + d];
            float zz = fmaf(w4.x, r4.x, fmaf(w4.y, r4.y, fmaf(w4.z, r4.z, fmaf(w4.w, r4.w, bias))));
            float delta = sp(zz);
            float a = __expf(delta * Aval);
            Bp0 = fmaf(Bp0, a, delta * Bs * x);
            Ap0 *= a;
        }
        {   // chain 1
            int j = j1 + i;
            int jm = (k >= 2) ? 4095 - j : j;
            int pos = (k & 1) ? ltmap(jm) : jm;
            float4 r4 = *(const float4*)(rec + (size_t)j * 8);
            float Bs = rec[(size_t)j * 8 + 4];
            float x = xb[(size_t)pos * 128 + d];
            float zz = fmaf(w4.x, r4.x, fmaf(w4.y, r4.y, fmaf(w4.z, r4.z, fmaf(w4.w, r4.w, bias))));
            float delta = sp(zz);
            float a = __expf(delta * Aval);
            Bp1 = fmaf(Bp1, a, delta * Bs * x);
            Ap1 *= a;
        }
    }
    g_aggA[(ebk * CH + cp * 2) * 128 + d] = Ap0;
    g_aggB[(ebk * CH + cp * 2) * 128 + d] = Bp0;
    g_aggA[(ebk * CH + cp * 2 + 1) * 128 + d] = Ap1;
    g_aggB[(ebk * CH + cp * 2 + 1) * 128 + d] = Bp1;
}

// ---------------- K4b: scan pass 2 — prefix across chunks -------------------
__global__ void k4b_scan_prefix()
{
    int ebk = blockIdx.x;    // 0..63
    int d = threadIdx.x;
    float h = 0.f;
    #pragma unroll
    for (int c = 0; c < CH; c++) {
        int idx = (ebk * CH + c) * 128 + d;
        float A = g_aggA[idx], Bv = g_aggB[idx];
        g_pref[idx] = h;
        h = fmaf(A, h, Bv);
    }
}

// ----- K4c: scan pass 3 — paired dirs (p, p+2), summed plane, NO smem -------
__global__ __launch_bounds__(128) void k4c_pair(
    const float* __restrict__ dtw, const float* __restrict__ dtb,
    const float* __restrict__ alogs, const float* __restrict__ dsv)
{
    int blk = blockIdx.x;                // eb*128 + p*64 + hc
    int hc = blk & 63;
    int p = (blk >> 6) & 1;
    int eb = blk >> 7;
    int e = eb >> 3;
    int d = threadIdx.x;
    int kf = p, kb = p + 2;
    int ebkf = eb * 4 + kf, ebkb = eb * 4 + kb;
    int kdf = (e * 4 + kf) * 128 + d;
    int kdb = (e * 4 + kb) * 128 + d;
    float4 wf = *(const float4*)&dtw[kdf * 4];
    float4 wb = *(const float4*)&dtw[kdb * 4];
    float biasf = dtb[kdf], biasb = dtb[kdb];
    float Avf = -expf(alogs[kdf]), Avb = -expf(alogs[kdb]);
    float Dvf = dsv[kdf], Dvb = dsv[kdb];
    const float* xb = g_xc + (size_t)eb * 4096 * 128;
    const float* recf = g_rec + (size_t)ebkf * 4096 * 8;
    const float* recb = g_rec + (size_t)ebkb * 4096 * 8;
    float* outp = (p ? g_ysB : g_ysA) + ((size_t)eb * 4096 + hc * CLEN) * 128 + d;
    // dir p+2, its chunk (63-hc), time-forward = i descending; write y2
    float hb = g_pref[(ebkb * CH + (CH - 1 - hc)) * 128 + d];
    #pragma unroll 4
    for (int i = CLEN - 1; i >= 0; i--) {
        int jj = hc * CLEN + i;
        int pos = p ? ltmap(jj) : jj;
        int jb = 4095 - jj;
        const float* rp = recb + (size_t)jb * 8;
        float4 r4 = *(const float4*)rp;
        float Bs = rp[4], Cs = rp[5];
        float x = xb[(size_t)pos * 128 + d];
        float zz = fmaf(wb.x, r4.x, fmaf(wb.y, r4.y, fmaf(wb.z, r4.z, fmaf(wb.w, r4.w, biasb))));
        float delta = sp(zz);
        float a = __expf(delta * Avb);
        hb = fmaf(a, hb, delta * Bs * x);
        outp[(size_t)i * 128] = fmaf(hb, Cs, Dvb * x);
    }
    // dir p, chunk hc, forward; add y1
    float hf = g_pref[(ebkf * CH + hc) * 128 + d];
    #pragma unroll 4
    for (int i = 0; i < CLEN; i++) {
        int jj = hc * CLEN + i;
        int pos = p ? ltmap(jj) : jj;
        const float* rp = recf + (size_t)jj * 8;
        float4 r4 = *(const float4*)rp;
        float Bs = rp[4], Cs = rp[5];
        float x = xb[(size_t)pos * 128 + d];
        float zz = fmaf(wf.x, r4.x, fmaf(wf.y, r4.y, fmaf(wf.z, r4.z, fmaf(wf.w, r4.w, biasf))));
        float delta = sp(zz);
        float a = __expf(delta * Avf);
        hf = fmaf(a, hf, delta * Bs * x);
        float y1 = fmaf(hf, Cs, Dvf * x);
        outp[(size_t)i * 128] += y1;
    }
}

// -- K6: sum 2 planes + LN*z + out_proj (128->64) via tensor cores + resid ---
__global__ __launch_bounds__(128) void k6_mma(
    const float* __restrict__ mag, const float* __restrict__ phase,
    const float* __restrict__ onw, const float* __restrict__ onb)
{
    __shared__ float syf[32 * 128];
    __shared__ __nv_bfloat16 sAh[32 * 136];
    __shared__ __nv_bfloat16 sAl[32 * 136];
    __shared__ float smu[32], srs[32];
    int row0 = blockIdx.x * 32;
    int e = row0 >> 15;
    int ebbase = row0 & ~4095;       // eb*4096
    int t = threadIdx.x;
    int lane = t & 31, wid = t >> 5;
    int group = lane >> 2, tig = lane & 3;
    {
        int r = t >> 2, c0 = (t & 3) * 32;
        int s = (row0 & 4095) + r;
        int jj = ltmap(s);
        const float* pA = &g_ysA[(size_t)(row0 + r) * 128 + c0];
        const float* pB = &g_ysB[(size_t)(ebbase + jj) * 128 + c0];
        #pragma unroll
        for (int i = 0; i < 8; i++) {
            float4 vA = *(const float4*)&pA[4 * i];
            float4 vB = *(const float4*)&pB[4 * i];
            syf[r * 128 + c0 + 4*i + 0] = vA.x + vB.x;
            syf[r * 128 + c0 + 4*i + 1] = vA.y + vB.y;
            syf[r * 128 + c0 + 4*i + 2] = vA.z + vB.z;
            syf[r * 128 + c0 + 4*i + 3] = vA.w + vB.w;
        }
    }
    __syncthreads();
    if (t < 32) {
        float s = 0.f, s2 = 0.f;
        #pragma unroll 8
        for (int i = 0; i < 128; i++) { float v = syf[t * 128 + i]; s += v; s2 += v * v; }
        float mu = s * (1.f / 128.f);
        smu[t] = mu;
        srs[t] = rsqrtf(fmaxf(s2 * (1.f / 128.f) - mu * mu, 0.f) + 1e-5f);
    }
    __syncthreads();
    #pragma unroll
    for (int idx = 0; idx < 32; idx++) {
        int q = idx * 128 + t;
        int rr = q >> 7, cc = q & 127;
        float v = (syf[rr * 128 + cc] - smu[rr]) * srs[rr] * onw[e * 128 + cc] + onb[e * 128 + cc];
        v *= g_z[(size_t)(row0 + rr) * 128 + cc];
        __nv_bfloat16 h = __float2bfloat16(v);
        sAh[rr * 136 + cc] = h;
        sAl[rr * 136 + cc] = __float2bfloat16(v - __bfloat162float(h));
    }
    __syncthreads();
    // GEMM C[32,64] = A[32,128] * Wop^T
    int mt = wid & 1;
    int nb2 = (wid >> 1) * 32;
    float c2[4][4];
    #pragma unroll
    for (int i = 0; i < 4; i++)
        { c2[i][0] = 0.f; c2[i][1] = 0.f; c2[i][2] = 0.f; c2[i][3] = 0.f; }
    #pragma unroll
    for (int ks = 0; ks < 8; ks++) {
        int ar = mt * 16 + group;
        int kk = ks * 16 + tig * 2;
        unsigned ah0 = *(const unsigned*)(sAh + ar * 136 + kk);
        unsigned ah1 = *(const unsigned*)(sAh + (ar + 8) * 136 + kk);
        unsigned ah2 = *(const unsigned*)(sAh + ar * 136 + kk + 8);
        unsigned ah3 = *(const unsigned*)(sAh + (ar + 8) * 136 + kk + 8);
        unsigned al0 = *(const unsigned*)(sAl + ar * 136 + kk);
        unsigned al1 = *(const unsigned*)(sAl + (ar + 8) * 136 + kk);
        unsigned al2 = *(const unsigned*)(sAl + ar * 136 + kk + 8);
        unsigned al3 = *(const unsigned*)(sAl + (ar + 8) * 136 + kk + 8);
        const uint2* wbase = g_wop + (size_t)(e * 64 + nb2 + group) * 64 + ks * 8 + tig;
        #pragma unroll
        for (int nt = 0; nt < 4; nt++) {
            const uint2* wp = wbase + nt * 512;   // n += 8 -> +8*64 pairs
            uint2 v0 = wp[0];
            uint2 v1 = wp[4];
            mma16816(c2[nt], ah0, ah1, ah2, ah3, v0.x, v1.x);
            mma16816(c2[nt], ah0, ah1, ah2, ah3, v0.y, v1.y);
            mma16816(c2[nt], al0, al1, al2, al3, v0.x, v1.x);
        }
    }
    const float* xin = e ? phase : mag;
    int rl0 = row0 & 32767;
    #pragma unroll
    for (int nt = 0; nt < 4; nt++) {
        int colb = nb2 + nt * 8 + tig * 2;
        int r0 = mt * 16 + group;
        float2 x0 = *(const float2*)&xin[(rl0 + r0) * 64 + colb];
        float2 x1 = *(const float2*)&xin[(rl0 + r0 + 8) * 64 + colb];
        *(float2*)&g_xres[(row0 + r0) * 64 + colb] =
            make_float2(c2[nt][0] + x0.x, c2[nt][1] + x0.y);
        *(float2*)&g_xres[(row0 + r0 + 8) * 64 + colb] =
            make_float2(c2[nt][2] + x1.x, c2[nt][3] + x1.y);
    }
}

// -------- K7: LN + fc1 + gelu + fc2 + residual — tensor-core bf16 split -----
__global__ __launch_bounds__(128) void k7_mlp_mma(
    const float* __restrict__ n2w, const float* __restrict__ n2b,
    const float* __restrict__ f1b, const float* __restrict__ f2b)
{
    __shared__ __align__(16) unsigned char smraw[43264];
    float* sxf = (float*)smraw;                              // 32x64 f32 (early)
    __nv_bfloat16* sHh = (__nv_bfloat16*)smraw;              // 32x264
    __nv_bfloat16* sHl = (__nv_bfloat16*)(smraw + 16896);
    __nv_bfloat16* sAh = (__nv_bfloat16*)(smraw + 33792);    // 32x72
    __nv_bfloat16* sAl = (__nv_bfloat16*)(smraw + 38400);
    float* smu = (float*)(smraw + 43008);
    float* srs = (float*)(smraw + 43136);

    int row0 = blockIdx.x * 32;
    int e = row0 >> 15;
    int t = threadIdx.x;
    int lane = t & 31, wid = t >> 5;
    int group = lane >> 2, tig = lane & 3;

    {
        int r = t >> 2, c0 = (t & 3) * 16;
        #pragma unroll
        for (int i = 0; i < 4; i++) {
            float4 v = *(const float4*)&g_xres[(row0 + r) * 64 + c0 + 4 * i];
            sxf[r * 64 + c0 + 4*i + 0] = v.x; sxf[r * 64 + c0 + 4*i + 1] = v.y;
            sxf[r * 64 + c0 + 4*i + 2] = v.z; sxf[r * 64 + c0 + 4*i + 3] = v.w;
        }
    }
    __syncthreads();
    if (t < 32) {
        float s = 0.f, s2 = 0.f;
        #pragma unroll
        for (int i = 0; i < 64; i++) { float v = sxf[t * 64 + i]; s += v; s2 += v * v; }
        float mu = s * (1.f / 64.f);
        smu[t] = mu;
        srs[t] = rsqrtf(fmaxf(s2 * (1.f / 64.f) - mu * mu, 0.f) + 1e-5f);
    }
    __syncthreads();
    #pragma unroll
    for (int idx = 0; idx < 16; idx++) {
        int q = idx * 128 + t;           // 0..2047
        int rr = q >> 6, cc = q & 63;
        float v = (sxf[rr * 64 + cc] - smu[rr]) * srs[rr] * n2w[e * 64 + cc] + n2b[e * 64 + cc];
        __nv_bfloat16 h = __float2bfloat16(v);
        sAh[rr * 72 + cc] = h;
        sAl[rr * 72 + cc] = __float2bfloat16(v - __bfloat162float(h));
    }
    __syncthreads();

    // fc1
    int mt = wid & 1;
    int nb = (wid >> 1) * 128;
    float c1[16][4];
    #pragma unroll
    for (int i = 0; i < 16; i++)
        { c1[i][0] = 0.f; c1[i][1] = 0.f; c1[i][2] = 0.f; c1[i][3] = 0.f; }
    #pragma unroll
    for (int ks = 0; ks < 4; ks++) {
        int ar = mt * 16 + group;
        int kk = ks * 16 + tig * 2;
        unsigned ah0 = *(const unsigned*)(sAh + ar * 72 + kk);
        unsigned ah1 = *(const unsigned*)(sAh + (ar + 8) * 72 + kk);
        unsigned ah2 = *(const unsigned*)(sAh + ar * 72 + kk + 8);
        unsigned ah3 = *(const unsigned*)(sAh + (ar + 8) * 72 + kk + 8);
        unsigned al0 = *(const unsigned*)(sAl + ar * 72 + kk);
        unsigned al1 = *(const unsigned*)(sAl + (ar + 8) * 72 + kk);
        unsigned al2 = *(const unsigned*)(sAl + ar * 72 + kk + 8);
        unsigned al3 = *(const unsigned*)(sAl + (ar + 8) * 72 + kk + 8);
        const uint2* wbase = g_w1p + (size_t)(e * 256 + nb + group) * 32 + ks * 8 + tig;
        #pragma unroll
        for (int nt = 0; nt < 16; nt++) {
            const uint2* wp = wbase + nt * 256;
            uint2 v0 = wp[0];
            uint2 v1 = wp[4];
            mma16816(c1[nt], ah0, ah1, ah2, ah3, v0.x, v1.x);
            mma16816(c1[nt], ah0, ah1, ah2, ah3, v0.y, v1.y);
            mma16816(c1[nt], al0, al1, al2, al3, v0.x, v1.x);
        }
    }
    #pragma unroll
    for (int nt = 0; nt < 16; nt++) {
        int colb = nb + nt * 8 + tig * 2;
        float2 b1 = *(const float2*)&f1b[e * 256 + colb];
        int r0 = mt * 16 + group;
        float g00 = geluf(c1[nt][0] + b1.x);
        float g01 = geluf(c1[nt][1] + b1.y);
        float g10 = geluf(c1[nt][2] + b1.x);
        float g11 = geluf(c1[nt][3] + b1.y);
        __nv_bfloat16 h;
        h = __float2bfloat16(g00); sHh[r0 * 264 + colb]           = h; sHl[r0 * 264 + colb]           = __float2bfloat16(g00 - __bfloat162float(h));
        h = __float2bfloat16(g01); sHh[r0 * 264 + colb + 1]       = h; sHl[r0 * 264 + colb + 1]       = __float2bfloat16(g01 - __bfloat162float(h));
        h = __float2bfloat16(g10); sHh[(r0 + 8) * 264 + colb]     = h; sHl[(r0 + 8) * 264 + colb]     = __float2bfloat16(g10 - __bfloat162float(h));
        h = __float2bfloat16(g11); sHh[(r0 + 8) * 264 + colb + 1] = h; sHl[(r0 + 8) * 264 + colb + 1] = __float2bfloat16(g11 - __bfloat162float(h));
    }
    __syncthreads();

    // fc2
    int nb2 = (wid >> 1) * 32;
    float c2[4][4];
    #pragma unroll
    for (int i = 0; i < 4; i++)
        { c2[i][0] = 0.f; c2[i][1] = 0.f; c2[i][2] = 0.f; c2[i][3] = 0.f; }
    #pragma unroll 4
    for (int ks = 0; ks < 16; ks++) {
        int ar = mt * 16 + group;
        int kk = ks * 16 + tig * 2;
        unsigned ah0 = *(const unsigned*)(sHh + ar * 264 + kk);
        unsigned ah1 = *(const unsigned*)(sHh + (ar + 8) * 264 + kk);
        unsigned ah2 = *(const unsigned*)(sHh + ar * 264 + kk + 8);
        unsigned ah3 = *(const unsigned*)(sHh + (ar + 8) * 264 + kk + 8);
        unsigned al0 = *(const unsigned*)(sHl + ar * 264 + kk);
        unsigned al1 = *(const unsigned*)(sHl + (ar + 8) * 264 + kk);
        unsigned al2 = *(const unsigned*)(sHl + ar * 264 + kk + 8);
        unsigned al3 = *(const unsigned*)(sHl + (ar + 8) * 264 + kk + 8);
        const uint2* wbase = g_w2p + (size_t)(e * 64 + nb2 + group) * 128 + ks * 8 + tig;
        #pragma unroll
        for (int nt = 0; nt < 4; nt++) {
            const uint2* wp = wbase + nt * 1024;
            uint2 v0 = wp[0];
            uint2 v1 = wp[4];
            mma16816(c2[nt], ah0, ah1, ah2, ah3, v0.x, v1.x);
            mma16816(c2[nt], ah0, ah1, ah2, ah3, v0.y, v1.y);
            mma16816(c2[nt], al0, al1, al2, al3, v0.x, v1.x);
        }
    }
    #pragma unroll
    for (int nt = 0; nt < 4; nt++) {
        int colb = nb2 + nt * 8 + tig * 2;
        float2 b2 = *(const float2*)&f2b[e * 64 + colb];
        int r0g = row0 + mt * 16 + group;
        float2 x0 = *(const float2*)&g_xres[r0g * 64 + colb];
        float2 x1 = *(const float2*)&g_xres[(r0g + 8) * 64 + colb];
        float2 o0 = make_float2(x0.x + c2[nt][0] + b2.x, x0.y + c2[nt][1] + b2.y);
        float2 o1 = make_float2(x1.x + c2[nt][2] + b2.x, x1.y + c2[nt][3] + b2.y);
        *(float2*)&g_mlp[r0g * 64 + colb] = o0;
        *(float2*)&g_mlp[(r0g + 8) * 64 + colb] = o1;
    }
}

// ---------------- K8: sum streams, duplicate output (float4) ----------------
__global__ void k8_final(float* __restrict__ out)
{
    int i = blockIdx.x * 256 + threadIdx.x;   // 0..524287 (float4 units)
    float4 a = *(const float4*)&g_mlp[4 * i];
    float4 b = *(const float4*)&g_mlp[4 * i + 2097152];
    float4 s = make_float4(a.x + b.x, a.y + b.y, a.z + b.z, a.w + b.w);
    *(float4*)&out[4 * i] = s;
    *(float4*)&out[4 * i + 2097152] = s;
}

// ---------------- launch ----------------------------------------------------
extern "C" void kernel_launch(void* const* d_in, const int* in_sizes, int n_in,
                              void* d_out, int out_size)
{
    const float* mag   = (const float*)d_in[0];
    const float* phase = (const float*)d_in[1];
    const float* n1w   = (const float*)d_in[2];
    const float* n1b   = (const float*)d_in[3];
    const float* ipw   = (const float*)d_in[4];
    const float* cvw   = (const float*)d_in[5];
    const float* xpw   = (const float*)d_in[6];
    const float* dtw   = (const float*)d_in[7];
    const float* dtb   = (const float*)d_in[8];
    const float* alg   = (const float*)d_in[9];
    const float* dsv   = (const float*)d_in[10];
    const float* onw   = (const float*)d_in[11];
    const float* onb   = (const float*)d_in[12];
    const float* opw   = (const float*)d_in[13];
    const float* n2w   = (const float*)d_in[14];
    const float* n2b   = (const float*)d_in[15];
    const float* f1w   = (const float*)d_in[16];
    const float* f1b   = (const float*)d_in[17];
    const float* f2w   = (const float*)d_in[18];
    const float* f2b   = (const float*)d_in[19];

    k0_prep<<<240, 256>>>(f1w, f2w, ipw, opw, xpw);
    k1_mma<<<2048, 128>>>(mag, phase, n1w, n1b);
    k2_conv<<<1024, 128>>>(cvw);
    k3_mma<<<1024, 256>>>();
    k4a_scan_partial<<<2048, 128>>>(dtw, dtb, alg);
    k4b_scan_prefix<<<64, 128>>>();
    k4c_pair<<<2048, 128>>>(dtw, dtb, alg, dsv);
    k6_mma<<<2048, 128>>>(mag, phase, onw, onb);
    k7_mlp_mma<<<2048, 128>>>(n2w, n2b, f1b, f2b);
    k8_final<<<2048, 256>>>((float*)d_out);
}